// round 1
// baseline (speedup 1.0000x reference)
#include <cuda_runtime.h>
#include <math.h>
#include <stdint.h>

// Problem constants
#define Bc 2
#define Tc 2048
#define Dc 2048
#define Hc 16
#define DSc 64
#define DGc 64
#define DHc 128
#define MROWS (Bc*Tc)          // 4096

// ---------------- scratch (device globals; no allocation allowed) -------------
__device__ float g_qs[MROWS * 1024];
__device__ float g_ks[MROWS * 1024];
__device__ float g_qg[MROWS * 1024];
__device__ float g_kg[MROWS * 1024];
__device__ float g_v [MROWS * 2048];
__device__ float g_qcat[Bc*Hc*Tc*128];
__device__ float g_kcat[Bc*Hc*Tc*128];
__device__ float g_ao [MROWS * 2048];

// ---------------- SGEMM: C[M,N] = A[M,K] @ B[K,N], all row-major --------------
// 128x128 block tile, BK=8, 256 threads, 8x8 per-thread micro-tile.
// Assumes M%128==0, N%128==0, K%8==0 (true for all calls here).
#define GBM 128
#define GBN 128
#define GBK 8

__global__ __launch_bounds__(256) void sgemm(const float* __restrict__ A,
                                             const float* __restrict__ B,
                                             float* __restrict__ C,
                                             int M, int N, int K) {
    __shared__ float As[GBK][GBM];
    __shared__ float Bs[GBK][GBN];
    const int tid = threadIdx.x;
    const int bm = blockIdx.y * GBM;
    const int bn = blockIdx.x * GBN;

    const int arow = tid >> 1;            // 0..127
    const int acol = (tid & 1) * 4;       // 0 or 4
    const int brow = tid >> 5;            // 0..7
    const int bcol = (tid & 31) * 4;      // 0..124

    const int tx = tid & 15;              // col group
    const int ty = tid >> 4;              // row group

    float acc[8][8];
    #pragma unroll
    for (int i = 0; i < 8; i++)
        #pragma unroll
        for (int j = 0; j < 8; j++) acc[i][j] = 0.f;

    for (int kt = 0; kt < K; kt += GBK) {
        float4 av = *(const float4*)(A + (size_t)(bm + arow) * K + kt + acol);
        As[acol + 0][arow] = av.x;
        As[acol + 1][arow] = av.y;
        As[acol + 2][arow] = av.z;
        As[acol + 3][arow] = av.w;
        float4 bv = *(const float4*)(B + (size_t)(kt + brow) * N + bn + bcol);
        *(float4*)&Bs[brow][bcol] = bv;
        __syncthreads();

        #pragma unroll
        for (int k = 0; k < GBK; k++) {
            float a[8], b[8];
            #pragma unroll
            for (int i = 0; i < 8; i++) a[i] = As[k][ty * 8 + i];
            #pragma unroll
            for (int j = 0; j < 8; j++) b[j] = Bs[k][tx * 8 + j];
            #pragma unroll
            for (int i = 0; i < 8; i++)
                #pragma unroll
                for (int j = 0; j < 8; j++) acc[i][j] += a[i] * b[j];
        }
        __syncthreads();
    }

    #pragma unroll
    for (int i = 0; i < 8; i++) {
        const size_t row = (size_t)(bm + ty * 8 + i);
        #pragma unroll
        for (int j = 0; j < 8; j += 4) {
            float4 v = make_float4(acc[i][j], acc[i][j+1], acc[i][j+2], acc[i][j+3]);
            *(float4*)(C + row * N + bn + tx * 8 + j) = v;
        }
    }
}

// ---------------- RoPE + gate fusion: build Qcat/Kcat [B,H,T,128] -------------
// Qcat[:, :64]  = qs * 2*sigmoid(g) * (1/sqrt(64))
// Qcat[:, 64:]  = rope(qg) * (2 - 2*sigmoid(g)) * (1/sqrt(64))
// Kcat[:, :64]  = ks ;  Kcat[:, 64:] = rope(kg)
__global__ void fuse_rope(const float* __restrict__ qs, const float* __restrict__ ks,
                          const float* __restrict__ qg, const float* __restrict__ kg,
                          const float* __restrict__ gate_logit,
                          const int* __restrict__ pos_offset,
                          float* __restrict__ qcat, float* __restrict__ kcat) {
    const int row = blockIdx.x;              // (b*H + h)*T + t
    const int d   = threadIdx.x;             // 0..63
    const int t   = row % Tc;
    const int h   = (row / Tc) % Hc;
    const int b   = row / (Tc * Hc);

    const size_t src = ((size_t)(b * Tc + t)) * 1024 + h * 64 + d;
    const size_t dst = (size_t)row * 128;

    const float gate = 1.f / (1.f + expf(-gate_logit[h]));
    const float scale = 0.125f;              // 1/sqrt(64)
    const float gq_sem = 2.f * gate * scale;
    const float gq_geo = (2.f - 2.f * gate) * scale;

    qcat[dst + d] = qs[src] * gq_sem;
    kcat[dst + d] = ks[src];

    if (d < 32) {
        const float inv_freq = powf(10000.f, -(float)d / 32.f);
        const float ang = ((float)t + (float)(*pos_offset)) * inv_freq;
        const float c = cosf(ang), s = sinf(ang);
        const float q1 = qg[src], q2 = qg[src + 32];
        const float k1 = kg[src], k2 = kg[src + 32];
        qcat[dst + 64 + d]      = (q1 * c - q2 * s) * gq_geo;
        qcat[dst + 64 + d + 32] = (q2 * c + q1 * s) * gq_geo;
        kcat[dst + 64 + d]      = k1 * c - k2 * s;
        kcat[dst + 64 + d + 32] = k2 * c + k1 * s;
    }
}

// ---------------- Flash attention, fp32, causal, dqk=dv=128 -------------------
struct FlashSmem {
    float Q[64][129];
    float K[64][129];
    float V[64][129];
    float P[64][65];
    float M[64];
    float L[64];
    float Scale[64];
};

__global__ __launch_bounds__(256) void flash_kernel(const float* __restrict__ Qc,
                                                    const float* __restrict__ Kc,
                                                    const float* __restrict__ Vp,
                                                    float* __restrict__ Out) {
    extern __shared__ char smem_raw[];
    FlashSmem& sm = *reinterpret_cast<FlashSmem*>(smem_raw);

    const int qb = blockIdx.x;               // query tile (64 rows)
    const int bh = blockIdx.y;               // b*H + h
    const int b  = bh >> 4;
    const int h  = bh & 15;
    const int tid  = threadIdx.x;
    const int lane = tid & 31;
    const int w    = tid >> 5;
    const int tx   = tid & 15;
    const int ty   = tid >> 4;

    const float* Qg = Qc + ((size_t)bh * Tc + qb * 64) * 128;
    const float* Kg = Kc + (size_t)bh * Tc * 128;
    const float* Vg = Vp + (size_t)b * Tc * 2048 + h * 128;   // [B*T, D] layout

    // load Q tile
    for (int i = tid; i < 64 * 32; i += 256) {
        const int r = i >> 5, c4 = (i & 31) << 2;
        float4 v = *(const float4*)(Qg + r * 128 + c4);
        sm.Q[r][c4] = v.x; sm.Q[r][c4+1] = v.y; sm.Q[r][c4+2] = v.z; sm.Q[r][c4+3] = v.w;
    }
    if (tid < 64) { sm.M[tid] = -1e30f; sm.L[tid] = 0.f; }

    float o[4][8];
    #pragma unroll
    for (int i = 0; i < 4; i++)
        #pragma unroll
        for (int j = 0; j < 8; j++) o[i][j] = 0.f;
    __syncthreads();

    for (int kt = 0; kt <= qb; kt++) {
        // load K, V tiles
        for (int i = tid; i < 64 * 32; i += 256) {
            const int r = i >> 5, c4 = (i & 31) << 2;
            float4 kv = *(const float4*)(Kg + (size_t)(kt * 64 + r) * 128 + c4);
            sm.K[r][c4] = kv.x; sm.K[r][c4+1] = kv.y; sm.K[r][c4+2] = kv.z; sm.K[r][c4+3] = kv.w;
            float4 vv = *(const float4*)(Vg + (size_t)(kt * 64 + r) * 2048 + c4);
            sm.V[r][c4] = vv.x; sm.V[r][c4+1] = vv.y; sm.V[r][c4+2] = vv.z; sm.V[r][c4+3] = vv.w;
        }
        __syncthreads();

        // S = Q K^T : 4x4 per thread over k=128
        float s[4][4];
        #pragma unroll
        for (int i = 0; i < 4; i++)
            #pragma unroll
            for (int j = 0; j < 4; j++) s[i][j] = 0.f;
        for (int kk = 0; kk < 128; kk++) {
            float a[4], bb[4];
            #pragma unroll
            for (int i = 0; i < 4; i++) a[i] = sm.Q[ty * 4 + i][kk];
            #pragma unroll
            for (int j = 0; j < 4; j++) bb[j] = sm.K[tx * 4 + j][kk];
            #pragma unroll
            for (int i = 0; i < 4; i++)
                #pragma unroll
                for (int j = 0; j < 4; j++) s[i][j] += a[i] * bb[j];
        }
        // causal mask on the diagonal tile
        if (kt == qb) {
            #pragma unroll
            for (int i = 0; i < 4; i++) {
                const int q = ty * 4 + i;
                #pragma unroll
                for (int j = 0; j < 4; j++)
                    if (tx * 4 + j > q) s[i][j] = -1e30f;
            }
        }
        #pragma unroll
        for (int i = 0; i < 4; i++)
            #pragma unroll
            for (int j = 0; j < 4; j++)
                sm.P[ty * 4 + i][tx * 4 + j] = s[i][j];
        __syncthreads();

        // online softmax: warp w owns rows w*8 .. w*8+7
        for (int r8 = 0; r8 < 8; r8++) {
            const int row = w * 8 + r8;
            float v0 = sm.P[row][lane];
            float v1 = sm.P[row][lane + 32];
            float mx = fmaxf(v0, v1);
            #pragma unroll
            for (int off = 16; off; off >>= 1)
                mx = fmaxf(mx, __shfl_xor_sync(0xffffffff, mx, off));
            const float m_old = sm.M[row];
            const float m_new = fmaxf(m_old, mx);
            const float p0 = expf(v0 - m_new);
            const float p1 = expf(v1 - m_new);
            float sum = p0 + p1;
            #pragma unroll
            for (int off = 16; off; off >>= 1)
                sum += __shfl_xor_sync(0xffffffff, sum, off);
            sm.P[row][lane] = p0;
            sm.P[row][lane + 32] = p1;
            if (lane == 0) {
                const float sc = expf(m_old - m_new);
                sm.Scale[row] = sc;
                sm.M[row] = m_new;
                sm.L[row] = sm.L[row] * sc + sum;
            }
        }
        __syncthreads();

        // O = O*scale + P @ V : 4 rows x 8 cols per thread
        #pragma unroll
        for (int i = 0; i < 4; i++) {
            const float sc = sm.Scale[ty * 4 + i];
            #pragma unroll
            for (int j = 0; j < 8; j++) o[i][j] *= sc;
        }
        for (int kk = 0; kk < 64; kk++) {
            float a[4], bb[8];
            #pragma unroll
            for (int i = 0; i < 4; i++) a[i] = sm.P[ty * 4 + i][kk];
            #pragma unroll
            for (int j = 0; j < 8; j++) bb[j] = sm.V[kk][tx * 8 + j];
            #pragma unroll
            for (int i = 0; i < 4; i++)
                #pragma unroll
                for (int j = 0; j < 8; j++) o[i][j] += a[i] * bb[j];
        }
        __syncthreads();
    }

    // write: Out[(b*T + t), h*128 + c]
    #pragma unroll
    for (int i = 0; i < 4; i++) {
        const int row = ty * 4 + i;
        const float inv = 1.f / sm.L[row];
        const size_t base = ((size_t)b * Tc + qb * 64 + row) * 2048 + h * 128 + tx * 8;
        #pragma unroll
        for (int j = 0; j < 8; j++)
            Out[base + j] = o[i][j] * inv;
    }
}

// ---------------- host launch --------------------------------------------------
extern "C" void kernel_launch(void* const* d_in, const int* in_sizes, int n_in,
                              void* d_out, int out_size) {
    const float* x          = (const float*)d_in[0];
    const float* Wq_sem     = (const float*)d_in[1];
    const float* Wk_sem     = (const float*)d_in[2];
    const float* Wq_geo     = (const float*)d_in[3];
    const float* Wk_geo     = (const float*)d_in[4];
    const float* Wv         = (const float*)d_in[5];
    const float* Wo         = (const float*)d_in[6];
    const float* gate_logit = (const float*)d_in[7];
    const int*   pos_offset = (const int*)d_in[8];
    float* out = (float*)d_out;

    float *qs, *ks, *qg, *kg, *v, *qcat, *kcat, *ao;
    cudaGetSymbolAddress((void**)&qs,   g_qs);
    cudaGetSymbolAddress((void**)&ks,   g_ks);
    cudaGetSymbolAddress((void**)&qg,   g_qg);
    cudaGetSymbolAddress((void**)&kg,   g_kg);
    cudaGetSymbolAddress((void**)&v,    g_v);
    cudaGetSymbolAddress((void**)&qcat, g_qcat);
    cudaGetSymbolAddress((void**)&kcat, g_kcat);
    cudaGetSymbolAddress((void**)&ao,   g_ao);

    const dim3 blk(256);

    // projections
    sgemm<<<dim3(1024 / GBN, MROWS / GBM), blk>>>(x, Wq_sem, qs, MROWS, 1024, 2048);
    sgemm<<<dim3(1024 / GBN, MROWS / GBM), blk>>>(x, Wk_sem, ks, MROWS, 1024, 2048);
    sgemm<<<dim3(1024 / GBN, MROWS / GBM), blk>>>(x, Wq_geo, qg, MROWS, 1024, 2048);
    sgemm<<<dim3(1024 / GBN, MROWS / GBM), blk>>>(x, Wk_geo, kg, MROWS, 1024, 2048);
    sgemm<<<dim3(2048 / GBN, MROWS / GBM), blk>>>(x, Wv,     v,  MROWS, 2048, 2048);

    // RoPE + gate + scale fusion into concatenated 128-dim Q/K
    fuse_rope<<<Bc * Hc * Tc, 64>>>(qs, ks, qg, kg, gate_logit, pos_offset, qcat, kcat);

    // flash attention (causal)
    cudaFuncSetAttribute(flash_kernel, cudaFuncAttributeMaxDynamicSharedMemorySize,
                         (int)sizeof(FlashSmem));
    flash_kernel<<<dim3(Tc / 64, Bc * Hc), 256, sizeof(FlashSmem)>>>(qcat, kcat, v, ao);

    // output projection
    sgemm<<<dim3(2048 / GBN, MROWS / GBM), blk>>>(ao, Wo, out, MROWS, 2048, 2048);
}

// round 2
// speedup vs baseline: 1.2370x; 1.2370x over previous
#include <cuda_runtime.h>
#include <math.h>
#include <stdint.h>

// Problem constants
#define Bc 2
#define Tc 2048
#define Dc 2048
#define Hc 16
#define MROWS (Bc*Tc)          // 4096

// ---------------- scratch (device globals; no allocation allowed) -------------
__device__ float g_qs[MROWS * 1024];
__device__ float g_ks[MROWS * 1024];
__device__ float g_qg[MROWS * 1024];
__device__ float g_kg[MROWS * 1024];
__device__ float g_v [MROWS * 2048];
__device__ float g_qcat[Bc*Hc*Tc*128];
__device__ float g_kcat[Bc*Hc*Tc*128];
__device__ float g_ao [MROWS * 2048];

// ---------------- SGEMM: C[M,N] = A[M,K] @ B[K,N], all row-major --------------
#define GBM 128
#define GBN 128
#define GBK 8

__global__ __launch_bounds__(256) void sgemm(const float* __restrict__ A,
                                             const float* __restrict__ B,
                                             float* __restrict__ C,
                                             int M, int N, int K) {
    __shared__ float As[GBK][GBM];
    __shared__ float Bs[GBK][GBN];
    const int tid = threadIdx.x;
    const int bm = blockIdx.y * GBM;
    const int bn = blockIdx.x * GBN;

    const int arow = tid >> 1;
    const int acol = (tid & 1) * 4;
    const int brow = tid >> 5;
    const int bcol = (tid & 31) * 4;

    const int tx = tid & 15;
    const int ty = tid >> 4;

    float acc[8][8];
    #pragma unroll
    for (int i = 0; i < 8; i++)
        #pragma unroll
        for (int j = 0; j < 8; j++) acc[i][j] = 0.f;

    for (int kt = 0; kt < K; kt += GBK) {
        float4 av = *(const float4*)(A + (size_t)(bm + arow) * K + kt + acol);
        As[acol + 0][arow] = av.x;
        As[acol + 1][arow] = av.y;
        As[acol + 2][arow] = av.z;
        As[acol + 3][arow] = av.w;
        float4 bv = *(const float4*)(B + (size_t)(kt + brow) * N + bn + bcol);
        *(float4*)&Bs[brow][bcol] = bv;
        __syncthreads();

        #pragma unroll
        for (int k = 0; k < GBK; k++) {
            float a[8], b[8];
            #pragma unroll
            for (int i = 0; i < 8; i++) a[i] = As[k][ty * 8 + i];
            #pragma unroll
            for (int j = 0; j < 8; j++) b[j] = Bs[k][tx * 8 + j];
            #pragma unroll
            for (int i = 0; i < 8; i++)
                #pragma unroll
                for (int j = 0; j < 8; j++) acc[i][j] += a[i] * b[j];
        }
        __syncthreads();
    }

    #pragma unroll
    for (int i = 0; i < 8; i++) {
        const size_t row = (size_t)(bm + ty * 8 + i);
        #pragma unroll
        for (int j = 0; j < 8; j += 4) {
            float4 v = make_float4(acc[i][j], acc[i][j+1], acc[i][j+2], acc[i][j+3]);
            *(float4*)(C + row * N + bn + tx * 8 + j) = v;
        }
    }
}

// ---------------- RoPE + gate fusion: build Qcat/Kcat [B,H,T,128] -------------
__global__ void fuse_rope(const float* __restrict__ qs, const float* __restrict__ ks,
                          const float* __restrict__ qg, const float* __restrict__ kg,
                          const float* __restrict__ gate_logit,
                          const int* __restrict__ pos_offset,
                          float* __restrict__ qcat, float* __restrict__ kcat) {
    const int row = blockIdx.x;              // (b*H + h)*T + t
    const int d   = threadIdx.x;             // 0..63
    const int t   = row % Tc;
    const int h   = (row / Tc) % Hc;
    const int b   = row / (Tc * Hc);

    const size_t src = ((size_t)(b * Tc + t)) * 1024 + h * 64 + d;
    const size_t dst = (size_t)row * 128;

    const float gate = 1.f / (1.f + __expf(-gate_logit[h]));
    const float scale = 0.125f;              // 1/sqrt(64)
    const float gq_sem = 2.f * gate * scale;
    const float gq_geo = (2.f - 2.f * gate) * scale;

    qcat[dst + d] = qs[src] * gq_sem;
    kcat[dst + d] = ks[src];

    if (d < 32) {
        const float inv_freq = powf(10000.f, -(float)d / 32.f);
        const float ang = ((float)t + (float)(*pos_offset)) * inv_freq;
        const float c = cosf(ang), s = sinf(ang);
        const float q1 = qg[src], q2 = qg[src + 32];
        const float k1 = kg[src], k2 = kg[src + 32];
        qcat[dst + 64 + d]      = (q1 * c - q2 * s) * gq_geo;
        qcat[dst + 64 + d + 32] = (q2 * c + q1 * s) * gq_geo;
        kcat[dst + 64 + d]      = k1 * c - k2 * s;
        kcat[dst + 64 + d + 32] = k2 * c + k1 * s;
    }
}

// ---------------- Flash attention v2: BM=128, BN=64, register softmax ---------
// smem layout (floats):
//   Qs [128][132]  feature-major: Qs[f][row]
//   Ks [128][68]   feature-major: Ks[f][key]
//   Vs [64][132]   key-major:     Vs[key][col]
//   PT [64][132]   key-major:     PT[key][row]
#define SQ_SZ  (128*132)
#define SK_SZ  (128*68)
#define SV_SZ  (64*132)
#define SPT_SZ (64*132)
#define FLASH_SMEM_BYTES ((SQ_SZ + SK_SZ + SV_SZ + SPT_SZ) * 4)

__global__ __launch_bounds__(256) void flash2(const float* __restrict__ Qc,
                                              const float* __restrict__ Kc,
                                              const float* __restrict__ Vp,
                                              float* __restrict__ Out) {
    extern __shared__ float sm[];
    float* Qs = sm;
    float* Ks = Qs + SQ_SZ;
    float* Vs = Ks + SK_SZ;
    float* PT = Vs + SV_SZ;

    const int qb = gridDim.x - 1 - blockIdx.x;   // big CTAs first
    const int bh = blockIdx.y;
    const int b  = bh >> 4;
    const int h  = bh & 15;
    const int tid  = threadIdx.x;
    const int tx   = tid & 15;
    const int ty   = tid >> 4;

    const float* Qg = Qc + ((size_t)bh * Tc + qb * 128) * 128;
    const float* Kg = Kc + (size_t)bh * Tc * 128;
    const float* Vg = Vp + (size_t)b * Tc * 2048 + h * 128;

    // ---- load Q (transposed to feature-major) ----
    for (int i = tid; i < 4096; i += 256) {
        const int l = i & 31, c = i >> 5;
        const int r  = ((c & 15) << 3) + (l >> 2);
        const int f4 = ((c >> 4) << 2) + (l & 3);
        float4 v = *(const float4*)(Qg + r * 128 + f4 * 4);
        Qs[(4*f4 + 0) * 132 + r] = v.x;
        Qs[(4*f4 + 1) * 132 + r] = v.y;
        Qs[(4*f4 + 2) * 132 + r] = v.z;
        Qs[(4*f4 + 3) * 132 + r] = v.w;
    }

    float o[8][8];
    float M[8], L[8];
    #pragma unroll
    for (int i = 0; i < 8; i++) {
        M[i] = -1e30f; L[i] = 0.f;
        #pragma unroll
        for (int j = 0; j < 8; j++) o[i][j] = 0.f;
    }

    const int ntiles = 2 * qb + 2;
    for (int kt = 0; kt < ntiles; kt++) {
        __syncthreads();   // prev PV reads done; Q ready on first iter

        // ---- load K tile (transposed) + V tile (direct) ----
        for (int i = tid; i < 2048; i += 256) {
            const int l = i & 31, c = i >> 5;
            const int r  = ((c & 7) << 3) + (l >> 2);
            const int f4 = ((c >> 3) << 2) + (l & 3);
            float4 v = *(const float4*)(Kg + (size_t)(kt * 64 + r) * 128 + f4 * 4);
            Ks[(4*f4 + 0) * 68 + r] = v.x;
            Ks[(4*f4 + 1) * 68 + r] = v.y;
            Ks[(4*f4 + 2) * 68 + r] = v.z;
            Ks[(4*f4 + 3) * 68 + r] = v.w;
        }
        for (int i = tid; i < 2048; i += 256) {
            const int r = i >> 5, c4 = (i & 31) << 2;
            float4 v = *(const float4*)(Vg + (size_t)(kt * 64 + r) * 2048 + c4);
            *(float4*)&Vs[r * 132 + c4] = v;
        }
        __syncthreads();

        // ---- S = Q @ K^T : 8x4 per thread ----
        float s[8][4];
        #pragma unroll
        for (int i = 0; i < 8; i++)
            #pragma unroll
            for (int j = 0; j < 4; j++) s[i][j] = 0.f;

        #pragma unroll 4
        for (int kk = 0; kk < 128; kk++) {
            float4 a0 = *(const float4*)&Qs[kk * 132 + ty * 8];
            float4 a1 = *(const float4*)&Qs[kk * 132 + ty * 8 + 4];
            float4 b0 = *(const float4*)&Ks[kk * 68 + tx * 4];
            const float a[8] = {a0.x,a0.y,a0.z,a0.w,a1.x,a1.y,a1.z,a1.w};
            const float bb[4] = {b0.x,b0.y,b0.z,b0.w};
            #pragma unroll
            for (int i = 0; i < 8; i++)
                #pragma unroll
                for (int j = 0; j < 4; j++) s[i][j] += a[i] * bb[j];
        }

        // ---- causal mask on diagonal tiles ----
        if (kt >= 2 * qb) {
            #pragma unroll
            for (int i = 0; i < 8; i++) {
                const int gq = qb * 128 + ty * 8 + i;
                #pragma unroll
                for (int j = 0; j < 4; j++) {
                    const int gk = kt * 64 + tx * 4 + j;
                    if (gk > gq) s[i][j] = -1e30f;
                }
            }
        }

        // ---- online softmax in registers ----
        #pragma unroll
        for (int i = 0; i < 8; i++) {
            float mx = fmaxf(fmaxf(s[i][0], s[i][1]), fmaxf(s[i][2], s[i][3]));
            #pragma unroll
            for (int off = 8; off; off >>= 1)
                mx = fmaxf(mx, __shfl_xor_sync(0xffffffffu, mx, off));
            const float m_new = fmaxf(M[i], mx);
            const float sc = __expf(M[i] - m_new);
            float p0 = __expf(s[i][0] - m_new);
            float p1 = __expf(s[i][1] - m_new);
            float p2 = __expf(s[i][2] - m_new);
            float p3 = __expf(s[i][3] - m_new);
            float rs = (p0 + p1) + (p2 + p3);
            #pragma unroll
            for (int off = 8; off; off >>= 1)
                rs += __shfl_xor_sync(0xffffffffu, rs, off);
            M[i] = m_new;
            L[i] = L[i] * sc + rs;
            #pragma unroll
            for (int j = 0; j < 8; j++) o[i][j] *= sc;
            s[i][0] = p0; s[i][1] = p1; s[i][2] = p2; s[i][3] = p3;
        }

        // ---- stage P transposed: PT[key][row] ----
        #pragma unroll
        for (int j = 0; j < 4; j++) {
            float4 w0 = make_float4(s[0][j], s[1][j], s[2][j], s[3][j]);
            float4 w1 = make_float4(s[4][j], s[5][j], s[6][j], s[7][j]);
            *(float4*)&PT[(tx * 4 + j) * 132 + ty * 8]     = w0;
            *(float4*)&PT[(tx * 4 + j) * 132 + ty * 8 + 4] = w1;
        }
        __syncthreads();

        // ---- O += P @ V : 8x8 per thread ----
        #pragma unroll 4
        for (int kk = 0; kk < 64; kk++) {
            float4 a0 = *(const float4*)&PT[kk * 132 + ty * 8];
            float4 a1 = *(const float4*)&PT[kk * 132 + ty * 8 + 4];
            float4 b0 = *(const float4*)&Vs[kk * 132 + tx * 8];
            float4 b1 = *(const float4*)&Vs[kk * 132 + tx * 8 + 4];
            const float a[8]  = {a0.x,a0.y,a0.z,a0.w,a1.x,a1.y,a1.z,a1.w};
            const float bb[8] = {b0.x,b0.y,b0.z,b0.w,b1.x,b1.y,b1.z,b1.w};
            #pragma unroll
            for (int i = 0; i < 8; i++)
                #pragma unroll
                for (int j = 0; j < 8; j++) o[i][j] += a[i] * bb[j];
        }
    }

    // ---- write out: Out[(b*T + t)][h*128 + col] ----
    #pragma unroll
    for (int i = 0; i < 8; i++) {
        const float inv = 1.f / L[i];
        const size_t base = ((size_t)b * Tc + qb * 128 + ty * 8 + i) * 2048
                          + h * 128 + tx * 8;
        float4 v0 = make_float4(o[i][0]*inv, o[i][1]*inv, o[i][2]*inv, o[i][3]*inv);
        float4 v1 = make_float4(o[i][4]*inv, o[i][5]*inv, o[i][6]*inv, o[i][7]*inv);
        *(float4*)(Out + base)     = v0;
        *(float4*)(Out + base + 4) = v1;
    }
}

// ---------------- host launch --------------------------------------------------
extern "C" void kernel_launch(void* const* d_in, const int* in_sizes, int n_in,
                              void* d_out, int out_size) {
    const float* x          = (const float*)d_in[0];
    const float* Wq_sem     = (const float*)d_in[1];
    const float* Wk_sem     = (const float*)d_in[2];
    const float* Wq_geo     = (const float*)d_in[3];
    const float* Wk_geo     = (const float*)d_in[4];
    const float* Wv         = (const float*)d_in[5];
    const float* Wo         = (const float*)d_in[6];
    const float* gate_logit = (const float*)d_in[7];
    const int*   pos_offset = (const int*)d_in[8];
    float* out = (float*)d_out;

    float *qs, *ks, *qg, *kg, *v, *qcat, *kcat, *ao;
    cudaGetSymbolAddress((void**)&qs,   g_qs);
    cudaGetSymbolAddress((void**)&ks,   g_ks);
    cudaGetSymbolAddress((void**)&qg,   g_qg);
    cudaGetSymbolAddress((void**)&kg,   g_kg);
    cudaGetSymbolAddress((void**)&v,    g_v);
    cudaGetSymbolAddress((void**)&qcat, g_qcat);
    cudaGetSymbolAddress((void**)&kcat, g_kcat);
    cudaGetSymbolAddress((void**)&ao,   g_ao);

    const dim3 blk(256);

    // projections
    sgemm<<<dim3(1024 / GBN, MROWS / GBM), blk>>>(x, Wq_sem, qs, MROWS, 1024, 2048);
    sgemm<<<dim3(1024 / GBN, MROWS / GBM), blk>>>(x, Wk_sem, ks, MROWS, 1024, 2048);
    sgemm<<<dim3(1024 / GBN, MROWS / GBM), blk>>>(x, Wq_geo, qg, MROWS, 1024, 2048);
    sgemm<<<dim3(1024 / GBN, MROWS / GBM), blk>>>(x, Wk_geo, kg, MROWS, 1024, 2048);
    sgemm<<<dim3(2048 / GBN, MROWS / GBM), blk>>>(x, Wv,     v,  MROWS, 2048, 2048);

    // RoPE + gate + scale fusion into concatenated 128-dim Q/K
    fuse_rope<<<Bc * Hc * Tc, 64>>>(qs, ks, qg, kg, gate_logit, pos_offset, qcat, kcat);

    // flash attention (causal), BM=128 x BN=64
    cudaFuncSetAttribute(flash2, cudaFuncAttributeMaxDynamicSharedMemorySize,
                         FLASH_SMEM_BYTES);
    flash2<<<dim3(Tc / 128, Bc * Hc), 256, FLASH_SMEM_BYTES>>>(qcat, kcat, v, ao);

    // output projection
    sgemm<<<dim3(2048 / GBN, MROWS / GBM), blk>>>(ao, Wo, out, MROWS, 2048, 2048);
}

// round 3
// speedup vs baseline: 2.6538x; 2.1453x over previous
#include <cuda_runtime.h>
#include <math.h>
#include <stdint.h>

// Problem constants
#define Bc 2
#define Tc 2048
#define Dc 2048
#define Hc 16
#define MROWS (Bc*Tc)          // 4096

// ---------------- scratch (device globals; no allocation allowed) -------------
__device__ float g_qs[MROWS * 1024];
__device__ float g_ks[MROWS * 1024];
__device__ float g_qg[MROWS * 1024];
__device__ float g_kg[MROWS * 1024];
__device__ float g_v [MROWS * 2048];
__device__ float g_qcat[Bc*Hc*Tc*128];
__device__ float g_kcat[Bc*Hc*Tc*128];
__device__ float g_ao [MROWS * 2048];

// ---------------- tf32 helpers -------------------------------------------------
__device__ __forceinline__ uint32_t f2tf32(float f) {
    uint32_t u;
    asm("cvt.rna.tf32.f32 %0, %1;" : "=r"(u) : "f"(f));
    return u;
}

__device__ __forceinline__ void mma_tf32(float* c,
                                         uint32_t a0, uint32_t a1, uint32_t a2, uint32_t a3,
                                         uint32_t b0, uint32_t b1) {
    asm volatile("mma.sync.aligned.m16n8k8.row.col.f32.tf32.tf32.f32 "
                 "{%0,%1,%2,%3}, {%4,%5,%6,%7}, {%8,%9}, {%0,%1,%2,%3};"
                 : "+f"(c[0]), "+f"(c[1]), "+f"(c[2]), "+f"(c[3])
                 : "r"(a0), "r"(a1), "r"(a2), "r"(a3), "r"(b0), "r"(b1));
}

// ---------------- tf32 tensor-core GEMM: C[M,N] = A[M,K] @ B[K,N] --------------
// CTA tile 128x128, BK=16, 128 threads = 4 warps, warp tile 64x64.
// Atoms m16n8k8: per warp 4(M) x 8(N) atoms, 2 k-steps per BK.
#define TBK 16

__global__ __launch_bounds__(128, 2) void gemm_tf32(const float* __restrict__ A,
                                                    const float* __restrict__ B,
                                                    float* __restrict__ C,
                                                    int M, int N, int K) {
    __shared__ uint32_t As[2][TBK][132];   // k-major A (tf32 bits)
    __shared__ uint32_t Bs[2][TBK][136];   // k-major B (tf32 bits)

    const int tid  = threadIdx.x;
    const int lane = tid & 31;
    const int wid  = tid >> 5;
    const int warpRow = (wid >> 1) * 64;
    const int warpCol = (wid & 1) * 64;
    const int bm = blockIdx.y * 128;
    const int bn = blockIdx.x * 128;

    // gmem load mapping
    const int a_r0 = tid >> 2;            // 0..31 (row within tile, step 32)
    const int a_c4 = (tid & 3) * 4;       // k group
    const int b_n4 = (tid & 31) * 4;      // col group
    const int b_k0 = tid >> 5;            // 0..3 (k row, step 4)

    float acc[4][8][4];
    #pragma unroll
    for (int i = 0; i < 4; i++)
        #pragma unroll
        for (int j = 0; j < 8; j++)
            #pragma unroll
            for (int r = 0; r < 4; r++) acc[i][j][r] = 0.f;

    float4 pa[4], pb[4];
    const int nkt = K / TBK;

    // ---- prologue: tile 0 ----
    #pragma unroll
    for (int i = 0; i < 4; i++)
        pa[i] = *(const float4*)(A + (size_t)(bm + a_r0 + 32*i) * K + a_c4);
    #pragma unroll
    for (int i = 0; i < 4; i++)
        pb[i] = *(const float4*)(B + (size_t)(b_k0 + 4*i) * N + bn + b_n4);
    #pragma unroll
    for (int i = 0; i < 4; i++) {
        const int row = a_r0 + 32*i;
        As[0][a_c4+0][row] = f2tf32(pa[i].x);
        As[0][a_c4+1][row] = f2tf32(pa[i].y);
        As[0][a_c4+2][row] = f2tf32(pa[i].z);
        As[0][a_c4+3][row] = f2tf32(pa[i].w);
    }
    #pragma unroll
    for (int i = 0; i < 4; i++) {
        uint32_t* dst = &Bs[0][b_k0 + 4*i][b_n4];
        dst[0] = f2tf32(pb[i].x);
        dst[1] = f2tf32(pb[i].y);
        dst[2] = f2tf32(pb[i].z);
        dst[3] = f2tf32(pb[i].w);
    }
    __syncthreads();

    for (int kt = 0; kt < nkt; kt++) {
        const int buf = kt & 1;

        // prefetch next tile to regs
        if (kt + 1 < nkt) {
            const int k0 = (kt + 1) * TBK;
            #pragma unroll
            for (int i = 0; i < 4; i++)
                pa[i] = *(const float4*)(A + (size_t)(bm + a_r0 + 32*i) * K + k0 + a_c4);
            #pragma unroll
            for (int i = 0; i < 4; i++)
                pb[i] = *(const float4*)(B + (size_t)(k0 + b_k0 + 4*i) * N + bn + b_n4);
        }

        // compute on current buffer: 2 k-steps
        #pragma unroll
        for (int ks = 0; ks < 2; ks++) {
            const int kb = ks * 8;
            uint32_t af[4][4], bf[8][2];
            #pragma unroll
            for (int am = 0; am < 4; am++) {
                const int r0 = warpRow + am*16 + (lane >> 2);
                af[am][0] = As[buf][kb + (lane & 3)    ][r0];
                af[am][1] = As[buf][kb + (lane & 3)    ][r0 + 8];
                af[am][2] = As[buf][kb + (lane & 3) + 4][r0];
                af[am][3] = As[buf][kb + (lane & 3) + 4][r0 + 8];
            }
            #pragma unroll
            for (int an = 0; an < 8; an++) {
                const int c0 = warpCol + an*8 + (lane >> 2);
                bf[an][0] = Bs[buf][kb + (lane & 3)    ][c0];
                bf[an][1] = Bs[buf][kb + (lane & 3) + 4][c0];
            }
            #pragma unroll
            for (int am = 0; am < 4; am++)
                #pragma unroll
                for (int an = 0; an < 8; an++)
                    mma_tf32(acc[am][an], af[am][0], af[am][1], af[am][2], af[am][3],
                             bf[an][0], bf[an][1]);
        }

        // store prefetched tile into other buffer
        if (kt + 1 < nkt) {
            const int nb = buf ^ 1;
            #pragma unroll
            for (int i = 0; i < 4; i++) {
                const int row = a_r0 + 32*i;
                As[nb][a_c4+0][row] = f2tf32(pa[i].x);
                As[nb][a_c4+1][row] = f2tf32(pa[i].y);
                As[nb][a_c4+2][row] = f2tf32(pa[i].z);
                As[nb][a_c4+3][row] = f2tf32(pa[i].w);
            }
            #pragma unroll
            for (int i = 0; i < 4; i++) {
                uint32_t* dst = &Bs[nb][b_k0 + 4*i][b_n4];
                dst[0] = f2tf32(pb[i].x);
                dst[1] = f2tf32(pb[i].y);
                dst[2] = f2tf32(pb[i].z);
                dst[3] = f2tf32(pb[i].w);
            }
        }
        __syncthreads();
    }

    // epilogue
    #pragma unroll
    for (int am = 0; am < 4; am++) {
        const int r0 = bm + warpRow + am*16 + (lane >> 2);
        #pragma unroll
        for (int an = 0; an < 8; an++) {
            const int c0 = bn + warpCol + an*8 + (lane & 3)*2;
            *(float2*)(C + (size_t)r0 * N + c0)       = make_float2(acc[am][an][0], acc[am][an][1]);
            *(float2*)(C + (size_t)(r0 + 8) * N + c0) = make_float2(acc[am][an][2], acc[am][an][3]);
        }
    }
}

// ---------------- RoPE + gate fusion: build Qcat/Kcat [B,H,T,128] -------------
__global__ void fuse_rope(const float* __restrict__ qs, const float* __restrict__ ks,
                          const float* __restrict__ qg, const float* __restrict__ kg,
                          const float* __restrict__ gate_logit,
                          const int* __restrict__ pos_offset,
                          float* __restrict__ qcat, float* __restrict__ kcat) {
    const int row = blockIdx.x;              // (b*H + h)*T + t
    const int d   = threadIdx.x;             // 0..63
    const int t   = row % Tc;
    const int h   = (row / Tc) % Hc;
    const int b   = row / (Tc * Hc);

    const size_t src = ((size_t)(b * Tc + t)) * 1024 + h * 64 + d;
    const size_t dst = (size_t)row * 128;

    const float gate = 1.f / (1.f + __expf(-gate_logit[h]));
    const float scale = 0.125f;              // 1/sqrt(64)
    const float gq_sem = 2.f * gate * scale;
    const float gq_geo = (2.f - 2.f * gate) * scale;

    qcat[dst + d] = qs[src] * gq_sem;
    kcat[dst + d] = ks[src];

    if (d < 32) {
        const float inv_freq = powf(10000.f, -(float)d / 32.f);
        const float ang = ((float)t + (float)(*pos_offset)) * inv_freq;
        const float c = cosf(ang), s = sinf(ang);
        const float q1 = qg[src], q2 = qg[src + 32];
        const float k1 = kg[src], k2 = kg[src + 32];
        qcat[dst + 64 + d]      = (q1 * c - q2 * s) * gq_geo;
        qcat[dst + 64 + d + 32] = (q2 * c + q1 * s) * gq_geo;
        kcat[dst + 64 + d]      = k1 * c - k2 * s;
        kcat[dst + 64 + d + 32] = k2 * c + k1 * s;
    }
}

// ---------------- Flash attention v2: BM=128, BN=64, register softmax ---------
#define SQ_SZ  (128*132)
#define SK_SZ  (128*68)
#define SV_SZ  (64*132)
#define SPT_SZ (64*132)
#define FLASH_SMEM_BYTES ((SQ_SZ + SK_SZ + SV_SZ + SPT_SZ) * 4)

__global__ __launch_bounds__(256) void flash2(const float* __restrict__ Qc,
                                              const float* __restrict__ Kc,
                                              const float* __restrict__ Vp,
                                              float* __restrict__ Out) {
    extern __shared__ float sm[];
    float* Qs = sm;
    float* Ks = Qs + SQ_SZ;
    float* Vs = Ks + SK_SZ;
    float* PT = Vs + SV_SZ;

    const int qb = gridDim.x - 1 - blockIdx.x;   // big CTAs first
    const int bh = blockIdx.y;
    const int b  = bh >> 4;
    const int h  = bh & 15;
    const int tid  = threadIdx.x;
    const int tx   = tid & 15;
    const int ty   = tid >> 4;

    const float* Qg = Qc + ((size_t)bh * Tc + qb * 128) * 128;
    const float* Kg = Kc + (size_t)bh * Tc * 128;
    const float* Vg = Vp + (size_t)b * Tc * 2048 + h * 128;

    // ---- load Q (transposed to feature-major) ----
    for (int i = tid; i < 4096; i += 256) {
        const int l = i & 31, c = i >> 5;
        const int r  = ((c & 15) << 3) + (l >> 2);
        const int f4 = ((c >> 4) << 2) + (l & 3);
        float4 v = *(const float4*)(Qg + r * 128 + f4 * 4);
        Qs[(4*f4 + 0) * 132 + r] = v.x;
        Qs[(4*f4 + 1) * 132 + r] = v.y;
        Qs[(4*f4 + 2) * 132 + r] = v.z;
        Qs[(4*f4 + 3) * 132 + r] = v.w;
    }

    float o[8][8];
    float M[8], L[8];
    #pragma unroll
    for (int i = 0; i < 8; i++) {
        M[i] = -1e30f; L[i] = 0.f;
        #pragma unroll
        for (int j = 0; j < 8; j++) o[i][j] = 0.f;
    }

    const int ntiles = 2 * qb + 2;
    for (int kt = 0; kt < ntiles; kt++) {
        __syncthreads();

        for (int i = tid; i < 2048; i += 256) {
            const int l = i & 31, c = i >> 5;
            const int r  = ((c & 7) << 3) + (l >> 2);
            const int f4 = ((c >> 3) << 2) + (l & 3);
            float4 v = *(const float4*)(Kg + (size_t)(kt * 64 + r) * 128 + f4 * 4);
            Ks[(4*f4 + 0) * 68 + r] = v.x;
            Ks[(4*f4 + 1) * 68 + r] = v.y;
            Ks[(4*f4 + 2) * 68 + r] = v.z;
            Ks[(4*f4 + 3) * 68 + r] = v.w;
        }
        for (int i = tid; i < 2048; i += 256) {
            const int r = i >> 5, c4 = (i & 31) << 2;
            float4 v = *(const float4*)(Vg + (size_t)(kt * 64 + r) * 2048 + c4);
            *(float4*)&Vs[r * 132 + c4] = v;
        }
        __syncthreads();

        float s[8][4];
        #pragma unroll
        for (int i = 0; i < 8; i++)
            #pragma unroll
            for (int j = 0; j < 4; j++) s[i][j] = 0.f;

        #pragma unroll 4
        for (int kk = 0; kk < 128; kk++) {
            float4 a0 = *(const float4*)&Qs[kk * 132 + ty * 8];
            float4 a1 = *(const float4*)&Qs[kk * 132 + ty * 8 + 4];
            float4 b0 = *(const float4*)&Ks[kk * 68 + tx * 4];
            const float a[8] = {a0.x,a0.y,a0.z,a0.w,a1.x,a1.y,a1.z,a1.w};
            const float bb[4] = {b0.x,b0.y,b0.z,b0.w};
            #pragma unroll
            for (int i = 0; i < 8; i++)
                #pragma unroll
                for (int j = 0; j < 4; j++) s[i][j] += a[i] * bb[j];
        }

        if (kt >= 2 * qb) {
            #pragma unroll
            for (int i = 0; i < 8; i++) {
                const int gq = qb * 128 + ty * 8 + i;
                #pragma unroll
                for (int j = 0; j < 4; j++) {
                    const int gk = kt * 64 + tx * 4 + j;
                    if (gk > gq) s[i][j] = -1e30f;
                }
            }
        }

        #pragma unroll
        for (int i = 0; i < 8; i++) {
            float mx = fmaxf(fmaxf(s[i][0], s[i][1]), fmaxf(s[i][2], s[i][3]));
            #pragma unroll
            for (int off = 8; off; off >>= 1)
                mx = fmaxf(mx, __shfl_xor_sync(0xffffffffu, mx, off));
            const float m_new = fmaxf(M[i], mx);
            const float sc = __expf(M[i] - m_new);
            float p0 = __expf(s[i][0] - m_new);
            float p1 = __expf(s[i][1] - m_new);
            float p2 = __expf(s[i][2] - m_new);
            float p3 = __expf(s[i][3] - m_new);
            float rs = (p0 + p1) + (p2 + p3);
            #pragma unroll
            for (int off = 8; off; off >>= 1)
                rs += __shfl_xor_sync(0xffffffffu, rs, off);
            M[i] = m_new;
            L[i] = L[i] * sc + rs;
            #pragma unroll
            for (int j = 0; j < 8; j++) o[i][j] *= sc;
            s[i][0] = p0; s[i][1] = p1; s[i][2] = p2; s[i][3] = p3;
        }

        #pragma unroll
        for (int j = 0; j < 4; j++) {
            float4 w0 = make_float4(s[0][j], s[1][j], s[2][j], s[3][j]);
            float4 w1 = make_float4(s[4][j], s[5][j], s[6][j], s[7][j]);
            *(float4*)&PT[(tx * 4 + j) * 132 + ty * 8]     = w0;
            *(float4*)&PT[(tx * 4 + j) * 132 + ty * 8 + 4] = w1;
        }
        __syncthreads();

        #pragma unroll 4
        for (int kk = 0; kk < 64; kk++) {
            float4 a0 = *(const float4*)&PT[kk * 132 + ty * 8];
            float4 a1 = *(const float4*)&PT[kk * 132 + ty * 8 + 4];
            float4 b0 = *(const float4*)&Vs[kk * 132 + tx * 8];
            float4 b1 = *(const float4*)&Vs[kk * 132 + tx * 8 + 4];
            const float a[8]  = {a0.x,a0.y,a0.z,a0.w,a1.x,a1.y,a1.z,a1.w};
            const float bb[8] = {b0.x,b0.y,b0.z,b0.w,b1.x,b1.y,b1.z,b1.w};
            #pragma unroll
            for (int i = 0; i < 8; i++)
                #pragma unroll
                for (int j = 0; j < 8; j++) o[i][j] += a[i] * bb[j];
        }
    }

    #pragma unroll
    for (int i = 0; i < 8; i++) {
        const float inv = 1.f / L[i];
        const size_t base = ((size_t)b * Tc + qb * 128 + ty * 8 + i) * 2048
                          + h * 128 + tx * 8;
        float4 v0 = make_float4(o[i][0]*inv, o[i][1]*inv, o[i][2]*inv, o[i][3]*inv);
        float4 v1 = make_float4(o[i][4]*inv, o[i][5]*inv, o[i][6]*inv, o[i][7]*inv);
        *(float4*)(Out + base)     = v0;
        *(float4*)(Out + base + 4) = v1;
    }
}

// ---------------- host launch --------------------------------------------------
extern "C" void kernel_launch(void* const* d_in, const int* in_sizes, int n_in,
                              void* d_out, int out_size) {
    const float* x          = (const float*)d_in[0];
    const float* Wq_sem     = (const float*)d_in[1];
    const float* Wk_sem     = (const float*)d_in[2];
    const float* Wq_geo     = (const float*)d_in[3];
    const float* Wk_geo     = (const float*)d_in[4];
    const float* Wv         = (const float*)d_in[5];
    const float* Wo         = (const float*)d_in[6];
    const float* gate_logit = (const float*)d_in[7];
    const int*   pos_offset = (const int*)d_in[8];
    float* out = (float*)d_out;

    float *qs, *ks, *qg, *kg, *v, *qcat, *kcat, *ao;
    cudaGetSymbolAddress((void**)&qs,   g_qs);
    cudaGetSymbolAddress((void**)&ks,   g_ks);
    cudaGetSymbolAddress((void**)&qg,   g_qg);
    cudaGetSymbolAddress((void**)&kg,   g_kg);
    cudaGetSymbolAddress((void**)&v,    g_v);
    cudaGetSymbolAddress((void**)&qcat, g_qcat);
    cudaGetSymbolAddress((void**)&kcat, g_kcat);
    cudaGetSymbolAddress((void**)&ao,   g_ao);

    const dim3 blk(128);

    // projections (tf32 tensor cores)
    gemm_tf32<<<dim3(1024/128, MROWS/128), blk>>>(x, Wq_sem, qs, MROWS, 1024, 2048);
    gemm_tf32<<<dim3(1024/128, MROWS/128), blk>>>(x, Wk_sem, ks, MROWS, 1024, 2048);
    gemm_tf32<<<dim3(1024/128, MROWS/128), blk>>>(x, Wq_geo, qg, MROWS, 1024, 2048);
    gemm_tf32<<<dim3(1024/128, MROWS/128), blk>>>(x, Wk_geo, kg, MROWS, 1024, 2048);
    gemm_tf32<<<dim3(2048/128, MROWS/128), blk>>>(x, Wv,     v,  MROWS, 2048, 2048);

    // RoPE + gate + scale fusion into concatenated 128-dim Q/K
    fuse_rope<<<Bc * Hc * Tc, 64>>>(qs, ks, qg, kg, gate_logit, pos_offset, qcat, kcat);

    // flash attention (causal), BM=128 x BN=64
    cudaFuncSetAttribute(flash2, cudaFuncAttributeMaxDynamicSharedMemorySize,
                         FLASH_SMEM_BYTES);
    flash2<<<dim3(Tc / 128, Bc * Hc), 256, FLASH_SMEM_BYTES>>>(qcat, kcat, v, ao);

    // output projection (tf32 tensor cores)
    gemm_tf32<<<dim3(2048/128, MROWS/128), blk>>>(ao, Wo, out, MROWS, 2048, 2048);
}

// round 4
// speedup vs baseline: 3.0923x; 1.1652x over previous
#include <cuda_runtime.h>
#include <math.h>
#include <stdint.h>

// Problem constants
#define Bc 2
#define Tc 2048
#define Dc 2048
#define Hc 16
#define MROWS (Bc*Tc)          // 4096

// ---------------- scratch (device globals; no allocation allowed) -------------
__device__ float g_qs[MROWS * 1024];
__device__ float g_ks[MROWS * 1024];
__device__ float g_qg[MROWS * 1024];
__device__ float g_kg[MROWS * 1024];
__device__ float g_v [MROWS * 2048];
__device__ float g_vh[MROWS * 2048];
__device__ float g_vl[MROWS * 2048];
__device__ float g_qcat[Bc*Hc*Tc*128];
__device__ float g_kh  [Bc*Hc*Tc*128];
__device__ float g_kl  [Bc*Hc*Tc*128];
__device__ float g_ao [MROWS * 2048];

// ---------------- tf32 helpers -------------------------------------------------
__device__ __forceinline__ uint32_t f2tf32(float f) {
    uint32_t u;
    asm("cvt.rna.tf32.f32 %0, %1;" : "=r"(u) : "f"(f));
    return u;
}
__device__ __forceinline__ float tf32r(float x) {
    return __uint_as_float(f2tf32(x));
}

__device__ __forceinline__ void mma_tf32(float* c,
                                         uint32_t a0, uint32_t a1, uint32_t a2, uint32_t a3,
                                         uint32_t b0, uint32_t b1) {
    asm volatile("mma.sync.aligned.m16n8k8.row.col.f32.tf32.tf32.f32 "
                 "{%0,%1,%2,%3}, {%4,%5,%6,%7}, {%8,%9}, {%0,%1,%2,%3};"
                 : "+f"(c[0]), "+f"(c[1]), "+f"(c[2]), "+f"(c[3])
                 : "r"(a0), "r"(a1), "r"(a2), "r"(a3), "r"(b0), "r"(b1));
}

// ---------------- tf32 tensor-core GEMM: C[M,N] = A[M,K] @ B[K,N] --------------
#define TBK 16

__global__ __launch_bounds__(128, 2) void gemm_tf32(const float* __restrict__ A,
                                                    const float* __restrict__ B,
                                                    float* __restrict__ C,
                                                    int M, int N, int K) {
    __shared__ uint32_t As[2][TBK][132];
    __shared__ uint32_t Bs[2][TBK][136];

    const int tid  = threadIdx.x;
    const int lane = tid & 31;
    const int wid  = tid >> 5;
    const int warpRow = (wid >> 1) * 64;
    const int warpCol = (wid & 1) * 64;
    const int bm = blockIdx.y * 128;
    const int bn = blockIdx.x * 128;

    const int a_r0 = tid >> 2;
    const int a_c4 = (tid & 3) * 4;
    const int b_n4 = (tid & 31) * 4;
    const int b_k0 = tid >> 5;

    float acc[4][8][4];
    #pragma unroll
    for (int i = 0; i < 4; i++)
        #pragma unroll
        for (int j = 0; j < 8; j++)
            #pragma unroll
            for (int r = 0; r < 4; r++) acc[i][j][r] = 0.f;

    float4 pa[4], pb[4];
    const int nkt = K / TBK;

    #pragma unroll
    for (int i = 0; i < 4; i++)
        pa[i] = *(const float4*)(A + (size_t)(bm + a_r0 + 32*i) * K + a_c4);
    #pragma unroll
    for (int i = 0; i < 4; i++)
        pb[i] = *(const float4*)(B + (size_t)(b_k0 + 4*i) * N + bn + b_n4);
    #pragma unroll
    for (int i = 0; i < 4; i++) {
        const int row = a_r0 + 32*i;
        As[0][a_c4+0][row] = f2tf32(pa[i].x);
        As[0][a_c4+1][row] = f2tf32(pa[i].y);
        As[0][a_c4+2][row] = f2tf32(pa[i].z);
        As[0][a_c4+3][row] = f2tf32(pa[i].w);
    }
    #pragma unroll
    for (int i = 0; i < 4; i++) {
        uint32_t* dst = &Bs[0][b_k0 + 4*i][b_n4];
        dst[0] = f2tf32(pb[i].x);
        dst[1] = f2tf32(pb[i].y);
        dst[2] = f2tf32(pb[i].z);
        dst[3] = f2tf32(pb[i].w);
    }
    __syncthreads();

    for (int kt = 0; kt < nkt; kt++) {
        const int buf = kt & 1;

        if (kt + 1 < nkt) {
            const int k0 = (kt + 1) * TBK;
            #pragma unroll
            for (int i = 0; i < 4; i++)
                pa[i] = *(const float4*)(A + (size_t)(bm + a_r0 + 32*i) * K + k0 + a_c4);
            #pragma unroll
            for (int i = 0; i < 4; i++)
                pb[i] = *(const float4*)(B + (size_t)(k0 + b_k0 + 4*i) * N + bn + b_n4);
        }

        #pragma unroll
        for (int ks = 0; ks < 2; ks++) {
            const int kb = ks * 8;
            uint32_t af[4][4], bf[8][2];
            #pragma unroll
            for (int am = 0; am < 4; am++) {
                const int r0 = warpRow + am*16 + (lane >> 2);
                af[am][0] = As[buf][kb + (lane & 3)    ][r0];
                af[am][1] = As[buf][kb + (lane & 3)    ][r0 + 8];
                af[am][2] = As[buf][kb + (lane & 3) + 4][r0];
                af[am][3] = As[buf][kb + (lane & 3) + 4][r0 + 8];
            }
            #pragma unroll
            for (int an = 0; an < 8; an++) {
                const int c0 = warpCol + an*8 + (lane >> 2);
                bf[an][0] = Bs[buf][kb + (lane & 3)    ][c0];
                bf[an][1] = Bs[buf][kb + (lane & 3) + 4][c0];
            }
            #pragma unroll
            for (int am = 0; am < 4; am++)
                #pragma unroll
                for (int an = 0; an < 8; an++)
                    mma_tf32(acc[am][an], af[am][0], af[am][1], af[am][2], af[am][3],
                             bf[an][0], bf[an][1]);
        }

        if (kt + 1 < nkt) {
            const int nb = buf ^ 1;
            #pragma unroll
            for (int i = 0; i < 4; i++) {
                const int row = a_r0 + 32*i;
                As[nb][a_c4+0][row] = f2tf32(pa[i].x);
                As[nb][a_c4+1][row] = f2tf32(pa[i].y);
                As[nb][a_c4+2][row] = f2tf32(pa[i].z);
                As[nb][a_c4+3][row] = f2tf32(pa[i].w);
            }
            #pragma unroll
            for (int i = 0; i < 4; i++) {
                uint32_t* dst = &Bs[nb][b_k0 + 4*i][b_n4];
                dst[0] = f2tf32(pb[i].x);
                dst[1] = f2tf32(pb[i].y);
                dst[2] = f2tf32(pb[i].z);
                dst[3] = f2tf32(pb[i].w);
            }
        }
        __syncthreads();
    }

    #pragma unroll
    for (int am = 0; am < 4; am++) {
        const int r0 = bm + warpRow + am*16 + (lane >> 2);
        #pragma unroll
        for (int an = 0; an < 8; an++) {
            const int c0 = bn + warpCol + an*8 + (lane & 3)*2;
            *(float2*)(C + (size_t)r0 * N + c0)       = make_float2(acc[am][an][0], acc[am][an][1]);
            *(float2*)(C + (size_t)(r0 + 8) * N + c0) = make_float2(acc[am][an][2], acc[am][an][3]);
        }
    }
}

// ---------------- V hi/lo split ------------------------------------------------
__global__ __launch_bounds__(256) void split_v(const float* __restrict__ v,
                                               float* __restrict__ vh,
                                               float* __restrict__ vl) {
    const size_t i = ((size_t)blockIdx.x * 256 + threadIdx.x) * 4;
    float4 x = *(const float4*)(v + i);
    float4 h, l;
    h.x = tf32r(x.x); l.x = tf32r(x.x - h.x);
    h.y = tf32r(x.y); l.y = tf32r(x.y - h.y);
    h.z = tf32r(x.z); l.z = tf32r(x.z - h.z);
    h.w = tf32r(x.w); l.w = tf32r(x.w - h.w);
    *(float4*)(vh + i) = h;
    *(float4*)(vl + i) = l;
}

// ---------------- RoPE + gate fusion: Qcat fp32, Kcat hi/lo --------------------
__global__ void fuse_rope(const float* __restrict__ qs, const float* __restrict__ ks,
                          const float* __restrict__ qg, const float* __restrict__ kg,
                          const float* __restrict__ gate_logit,
                          const int* __restrict__ pos_offset,
                          float* __restrict__ qcat,
                          float* __restrict__ kh_o, float* __restrict__ kl_o) {
    const int row = blockIdx.x;              // (b*H + h)*T + t
    const int d   = threadIdx.x;             // 0..63
    const int t   = row % Tc;
    const int h   = (row / Tc) % Hc;
    const int b   = row / (Tc * Hc);

    const size_t src = ((size_t)(b * Tc + t)) * 1024 + h * 64 + d;
    const size_t dst = (size_t)row * 128;

    const float gate = 1.f / (1.f + __expf(-gate_logit[h]));
    const float scale = 0.125f;              // 1/sqrt(64)
    const float gq_sem = 2.f * gate * scale;
    const float gq_geo = (2.f - 2.f * gate) * scale;

    qcat[dst + d] = qs[src] * gq_sem;
    {
        const float kv = ks[src];
        const float kh = tf32r(kv);
        kh_o[dst + d] = kh;
        kl_o[dst + d] = tf32r(kv - kh);
    }

    if (d < 32) {
        const float inv_freq = powf(10000.f, -(float)d / 32.f);
        const float ang = ((float)t + (float)(*pos_offset)) * inv_freq;
        const float c = cosf(ang), s = sinf(ang);
        const float q1 = qg[src], q2 = qg[src + 32];
        const float k1 = kg[src], k2 = kg[src + 32];
        qcat[dst + 64 + d]      = (q1 * c - q2 * s) * gq_geo;
        qcat[dst + 64 + d + 32] = (q2 * c + q1 * s) * gq_geo;
        const float ka = k1 * c - k2 * s;
        const float kb = k2 * c + k1 * s;
        const float kah = tf32r(ka), kbh = tf32r(kb);
        kh_o[dst + 64 + d]      = kah;
        kl_o[dst + 64 + d]      = tf32r(ka - kah);
        kh_o[dst + 64 + d + 32] = kbh;
        kl_o[dst + 64 + d + 32] = tf32r(kb - kbh);
    }
}

// ---------------- Flash attention v3: 3xTF32 tensor cores ---------------------
// BM=128 (8 warps x 16 rows), BN=64. Q fp32 in regs; K/V hi+lo tiles in smem.
#define FSM_KH 0
#define FSM_KL (64*132)
#define FSM_VH (2*64*132)
#define FSM_VL (2*64*132 + 64*136)
#define FSM_P  (2*64*132 + 2*64*136)
#define FLASH3_SMEM_FLOATS (2*64*132 + 2*64*136 + 128*68)
#define FLASH3_SMEM_BYTES  (FLASH3_SMEM_FLOATS * 4)

__global__ __launch_bounds__(256, 1) void flash3(
    const float* __restrict__ Qc,
    const float* __restrict__ Khg, const float* __restrict__ Klg,
    const float* __restrict__ Vhg, const float* __restrict__ Vlg,
    float* __restrict__ Out)
{
    extern __shared__ float sm[];
    float* sKh = sm + FSM_KH;    // [64][132] keys x feats
    float* sKl = sm + FSM_KL;
    float* sVh = sm + FSM_VH;    // [64][136] keys x vcols
    float* sVl = sm + FSM_VL;
    float* sP  = sm + FSM_P;     // [128][68] rows x keys

    const int qb = gridDim.x - 1 - blockIdx.x;   // heavy CTAs first
    const int bh = blockIdx.y;
    const int b  = bh >> 4, h = bh & 15;
    const int tid  = threadIdx.x;
    const int lane = tid & 31;
    const int wid  = tid >> 5;
    const int g = lane >> 2;     // group id (row within atom)
    const int t = lane & 3;      // thread-in-group (k / col pair)
    const int r0 = wid * 16 + g; // this thread's base row in the 128-row tile

    const float* Qg   = Qc  + ((size_t)bh * Tc + qb * 128) * 128;
    const float* Kh_p = Khg + (size_t)bh * Tc * 128;
    const float* Kl_p = Klg + (size_t)bh * Tc * 128;
    const float* Vh_p = Vhg + (size_t)b * Tc * 2048 + h * 128;
    const float* Vl_p = Vlg + (size_t)b * Tc * 2048 + h * 128;

    // ---- stage Q through smem (reuses K region), pull A-fragments to regs ----
    for (int i = tid; i < 4096; i += 256) {
        const int r = i >> 5, c4 = (i & 31) << 2;
        *(float4*)&sm[r * 132 + c4] = *(const float4*)(Qg + r * 128 + c4);
    }
    __syncthreads();
    float qf[16][4];
    #pragma unroll
    for (int ks = 0; ks < 16; ks++) {
        qf[ks][0] = sm[ r0      * 132 + ks*8 + t];
        qf[ks][1] = sm[(r0 + 8) * 132 + ks*8 + t];
        qf[ks][2] = sm[ r0      * 132 + ks*8 + t + 4];
        qf[ks][3] = sm[(r0 + 8) * 132 + ks*8 + t + 4];
    }

    float oreg[16][4];
    #pragma unroll
    for (int n = 0; n < 16; n++) {
        oreg[n][0] = 0.f; oreg[n][1] = 0.f; oreg[n][2] = 0.f; oreg[n][3] = 0.f;
    }
    float M0 = -1e30f, M1 = -1e30f, L0 = 0.f, L1 = 0.f;

    const uint32_t* uKh = (const uint32_t*)sKh;
    const uint32_t* uKl = (const uint32_t*)sKl;
    const uint32_t* uVh = (const uint32_t*)sVh;
    const uint32_t* uVl = (const uint32_t*)sVl;

    const int ntiles = 2 * qb + 2;
    for (int kt = 0; kt < ntiles; kt++) {
        __syncthreads();   // prior consumers done (incl. Q staging on iter 0)
        for (int i = tid; i < 2048; i += 256) {
            const int r = i >> 5, c4 = (i & 31) << 2;
            const size_t krow = (size_t)(kt * 64 + r);
            *(float4*)&sKh[r*132 + c4] = *(const float4*)(Kh_p + krow*128  + c4);
            *(float4*)&sKl[r*132 + c4] = *(const float4*)(Kl_p + krow*128  + c4);
            *(float4*)&sVh[r*136 + c4] = *(const float4*)(Vh_p + krow*2048 + c4);
            *(float4*)&sVl[r*136 + c4] = *(const float4*)(Vl_p + krow*2048 + c4);
        }
        __syncthreads();

        // ---- S = Q K^T (3xTF32), 8 n-atoms per warp ----
        float sreg[8][4];
        #pragma unroll
        for (int n = 0; n < 8; n++) {
            sreg[n][0] = 0.f; sreg[n][1] = 0.f; sreg[n][2] = 0.f; sreg[n][3] = 0.f;
        }
        #pragma unroll
        for (int ks = 0; ks < 16; ks++) {
            uint32_t ah[4], al[4];
            #pragma unroll
            for (int e = 0; e < 4; e++) {
                ah[e] = f2tf32(qf[ks][e]);
                al[e] = f2tf32(qf[ks][e] - __uint_as_float(ah[e]));
            }
            const int kb = ks*8 + t;
            #pragma unroll
            for (int n = 0; n < 8; n++) {
                const int kr = n*8 + g;
                const uint32_t bh0 = uKh[kr*132 + kb], bh1 = uKh[kr*132 + kb + 4];
                const uint32_t bl0 = uKl[kr*132 + kb], bl1 = uKl[kr*132 + kb + 4];
                mma_tf32(sreg[n], ah[0], ah[1], ah[2], ah[3], bh0, bh1);
                mma_tf32(sreg[n], al[0], al[1], al[2], al[3], bh0, bh1);
                mma_tf32(sreg[n], ah[0], ah[1], ah[2], ah[3], bl0, bl1);
            }
        }

        // ---- causal mask (diagonal super-tiles) ----
        if (kt >= 2 * qb) {
            const int qrow0 = qb * 128 + r0;
            const int qrow1 = qrow0 + 8;
            #pragma unroll
            for (int n = 0; n < 8; n++) {
                const int c = kt * 64 + n*8 + 2*t;
                if (c     > qrow0) sreg[n][0] = -1e30f;
                if (c + 1 > qrow0) sreg[n][1] = -1e30f;
                if (c     > qrow1) sreg[n][2] = -1e30f;
                if (c + 1 > qrow1) sreg[n][3] = -1e30f;
            }
        }

        // ---- online softmax (rows r0, r0+8; reduce over quad lanes) ----
        float mx0 = -1e30f, mx1 = -1e30f;
        #pragma unroll
        for (int n = 0; n < 8; n++) {
            mx0 = fmaxf(mx0, fmaxf(sreg[n][0], sreg[n][1]));
            mx1 = fmaxf(mx1, fmaxf(sreg[n][2], sreg[n][3]));
        }
        mx0 = fmaxf(mx0, __shfl_xor_sync(0xffffffffu, mx0, 1));
        mx0 = fmaxf(mx0, __shfl_xor_sync(0xffffffffu, mx0, 2));
        mx1 = fmaxf(mx1, __shfl_xor_sync(0xffffffffu, mx1, 1));
        mx1 = fmaxf(mx1, __shfl_xor_sync(0xffffffffu, mx1, 2));
        const float mn0 = fmaxf(M0, mx0), mn1 = fmaxf(M1, mx1);
        const float sc0 = __expf(M0 - mn0), sc1 = __expf(M1 - mn1);
        float sum0 = 0.f, sum1 = 0.f;
        #pragma unroll
        for (int n = 0; n < 8; n++) {
            sreg[n][0] = __expf(sreg[n][0] - mn0); sum0 += sreg[n][0];
            sreg[n][1] = __expf(sreg[n][1] - mn0); sum0 += sreg[n][1];
            sreg[n][2] = __expf(sreg[n][2] - mn1); sum1 += sreg[n][2];
            sreg[n][3] = __expf(sreg[n][3] - mn1); sum1 += sreg[n][3];
        }
        sum0 += __shfl_xor_sync(0xffffffffu, sum0, 1);
        sum0 += __shfl_xor_sync(0xffffffffu, sum0, 2);
        sum1 += __shfl_xor_sync(0xffffffffu, sum1, 1);
        sum1 += __shfl_xor_sync(0xffffffffu, sum1, 2);
        M0 = mn0; M1 = mn1;
        L0 = L0 * sc0 + sum0;
        L1 = L1 * sc1 + sum1;
        #pragma unroll
        for (int n = 0; n < 16; n++) {
            oreg[n][0] *= sc0; oreg[n][1] *= sc0;
            oreg[n][2] *= sc1; oreg[n][3] *= sc1;
        }

        // ---- stage P into warp-private smem rows ----
        #pragma unroll
        for (int n = 0; n < 8; n++) {
            *(float2*)&sP[ r0      * 68 + n*8 + 2*t] = make_float2(sreg[n][0], sreg[n][1]);
            *(float2*)&sP[(r0 + 8) * 68 + n*8 + 2*t] = make_float2(sreg[n][2], sreg[n][3]);
        }
        __syncwarp();

        // ---- O += P V (3xTF32), 16 n-atoms per warp ----
        #pragma unroll
        for (int ks = 0; ks < 8; ks++) {
            float p0 = sP[ r0      * 68 + ks*8 + t];
            float p1 = sP[(r0 + 8) * 68 + ks*8 + t];
            float p2 = sP[ r0      * 68 + ks*8 + t + 4];
            float p3 = sP[(r0 + 8) * 68 + ks*8 + t + 4];
            uint32_t ah[4], al[4];
            ah[0] = f2tf32(p0); al[0] = f2tf32(p0 - __uint_as_float(ah[0]));
            ah[1] = f2tf32(p1); al[1] = f2tf32(p1 - __uint_as_float(ah[1]));
            ah[2] = f2tf32(p2); al[2] = f2tf32(p2 - __uint_as_float(ah[2]));
            ah[3] = f2tf32(p3); al[3] = f2tf32(p3 - __uint_as_float(ah[3]));
            const int kr0 = (ks*8 + t) * 136;
            const int kr1 = (ks*8 + t + 4) * 136;
            #pragma unroll
            for (int n = 0; n < 16; n++) {
                const int vc = n*8 + g;
                const uint32_t bh0 = uVh[kr0 + vc], bh1 = uVh[kr1 + vc];
                const uint32_t bl0 = uVl[kr0 + vc], bl1 = uVl[kr1 + vc];
                mma_tf32(oreg[n], ah[0], ah[1], ah[2], ah[3], bh0, bh1);
                mma_tf32(oreg[n], al[0], al[1], al[2], al[3], bh0, bh1);
                mma_tf32(oreg[n], ah[0], ah[1], ah[2], ah[3], bl0, bl1);
            }
        }
    }

    // ---- epilogue: Out[(b*T + t)][h*128 + col] ----
    const float inv0 = 1.f / L0, inv1 = 1.f / L1;
    const size_t row0 = (size_t)b * Tc + qb * 128 + r0;
    #pragma unroll
    for (int n = 0; n < 16; n++) {
        const int col = h * 128 + n*8 + 2*t;
        *(float2*)(Out +  row0      * 2048 + col) = make_float2(oreg[n][0]*inv0, oreg[n][1]*inv0);
        *(float2*)(Out + (row0 + 8) * 2048 + col) = make_float2(oreg[n][2]*inv1, oreg[n][3]*inv1);
    }
}

// ---------------- host launch --------------------------------------------------
extern "C" void kernel_launch(void* const* d_in, const int* in_sizes, int n_in,
                              void* d_out, int out_size) {
    const float* x          = (const float*)d_in[0];
    const float* Wq_sem     = (const float*)d_in[1];
    const float* Wk_sem     = (const float*)d_in[2];
    const float* Wq_geo     = (const float*)d_in[3];
    const float* Wk_geo     = (const float*)d_in[4];
    const float* Wv         = (const float*)d_in[5];
    const float* Wo         = (const float*)d_in[6];
    const float* gate_logit = (const float*)d_in[7];
    const int*   pos_offset = (const int*)d_in[8];
    float* out = (float*)d_out;

    float *qs, *ks, *qg, *kg, *v, *vh, *vl, *qcat, *kh, *kl, *ao;
    cudaGetSymbolAddress((void**)&qs,   g_qs);
    cudaGetSymbolAddress((void**)&ks,   g_ks);
    cudaGetSymbolAddress((void**)&qg,   g_qg);
    cudaGetSymbolAddress((void**)&kg,   g_kg);
    cudaGetSymbolAddress((void**)&v,    g_v);
    cudaGetSymbolAddress((void**)&vh,   g_vh);
    cudaGetSymbolAddress((void**)&vl,   g_vl);
    cudaGetSymbolAddress((void**)&qcat, g_qcat);
    cudaGetSymbolAddress((void**)&kh,   g_kh);
    cudaGetSymbolAddress((void**)&kl,   g_kl);
    cudaGetSymbolAddress((void**)&ao,   g_ao);

    const dim3 blk(128);

    // projections (tf32 tensor cores)
    gemm_tf32<<<dim3(1024/128, MROWS/128), blk>>>(x, Wq_sem, qs, MROWS, 1024, 2048);
    gemm_tf32<<<dim3(1024/128, MROWS/128), blk>>>(x, Wk_sem, ks, MROWS, 1024, 2048);
    gemm_tf32<<<dim3(1024/128, MROWS/128), blk>>>(x, Wq_geo, qg, MROWS, 1024, 2048);
    gemm_tf32<<<dim3(1024/128, MROWS/128), blk>>>(x, Wk_geo, kg, MROWS, 1024, 2048);
    gemm_tf32<<<dim3(2048/128, MROWS/128), blk>>>(x, Wv,     v,  MROWS, 2048, 2048);

    // V hi/lo split for 3xTF32 PV
    split_v<<<(MROWS * 2048) / (256 * 4), 256>>>(v, vh, vl);

    // RoPE + gate + scale fusion; K emitted as tf32 hi/lo
    fuse_rope<<<Bc * Hc * Tc, 64>>>(qs, ks, qg, kg, gate_logit, pos_offset,
                                    qcat, kh, kl);

    // flash attention (causal), 3xTF32 tensor cores
    cudaFuncSetAttribute(flash3, cudaFuncAttributeMaxDynamicSharedMemorySize,
                         FLASH3_SMEM_BYTES);
    flash3<<<dim3(Tc / 128, Bc * Hc), 256, FLASH3_SMEM_BYTES>>>(qcat, kh, kl, vh, vl, ao);

    // output projection (tf32 tensor cores)
    gemm_tf32<<<dim3(2048/128, MROWS/128), blk>>>(ao, Wo, out, MROWS, 2048, 2048);
}

// round 5
// speedup vs baseline: 3.7017x; 1.1971x over previous
#include <cuda_runtime.h>
#include <math.h>
#include <stdint.h>

// Problem constants
#define Bc 2
#define Tc 2048
#define Dc 2048
#define Hc 16
#define MROWS (Bc*Tc)          // 4096

// ---------------- scratch (device globals; no allocation allowed) -------------
__device__ float g_qs[MROWS * 1024];
__device__ float g_ks[MROWS * 1024];
__device__ float g_qg[MROWS * 1024];
__device__ float g_kg[MROWS * 1024];
__device__ float g_vt[MROWS * 2048];           // V, tf32-rounded
__device__ float g_qcat[Bc*Hc*Tc*128];
__device__ float g_kh  [Bc*Hc*Tc*128];
__device__ float g_kl  [Bc*Hc*Tc*128];
__device__ float g_ao [MROWS * 2048];

// ---------------- tf32 helpers -------------------------------------------------
__device__ __forceinline__ uint32_t f2tf32(float f) {
    uint32_t u;
    asm("cvt.rna.tf32.f32 %0, %1;" : "=r"(u) : "f"(f));
    return u;
}
__device__ __forceinline__ float tf32r(float x) {
    return __uint_as_float(f2tf32(x));
}

__device__ __forceinline__ void mma_tf32(float* c,
                                         uint32_t a0, uint32_t a1, uint32_t a2, uint32_t a3,
                                         uint32_t b0, uint32_t b1) {
    asm volatile("mma.sync.aligned.m16n8k8.row.col.f32.tf32.tf32.f32 "
                 "{%0,%1,%2,%3}, {%4,%5,%6,%7}, {%8,%9}, {%0,%1,%2,%3};"
                 : "+f"(c[0]), "+f"(c[1]), "+f"(c[2]), "+f"(c[3])
                 : "r"(a0), "r"(a1), "r"(a2), "r"(a3), "r"(b0), "r"(b1));
}

__device__ __forceinline__ void cp16(void* dst, const void* src) {
    uint32_t d = (uint32_t)__cvta_generic_to_shared(dst);
    asm volatile("cp.async.cg.shared.global [%0], [%1], 16;" :: "r"(d), "l"(src));
}
__device__ __forceinline__ void cp_commit() {
    asm volatile("cp.async.commit_group;");
}
__device__ __forceinline__ void cp_wait1() {
    asm volatile("cp.async.wait_group 1;");
}
__device__ __forceinline__ void cp_wait0() {
    asm volatile("cp.async.wait_group 0;");
}

// ---------------- tf32 tensor-core GEMM: C[M,N] = A[M,K] @ B[K,N] --------------
#define TBK 16

__global__ __launch_bounds__(128, 2) void gemm_tf32(const float* __restrict__ A,
                                                    const float* __restrict__ B,
                                                    float* __restrict__ C,
                                                    int M, int N, int K, int roundC) {
    __shared__ uint32_t As[2][TBK][132];
    __shared__ uint32_t Bs[2][TBK][136];

    const int tid  = threadIdx.x;
    const int lane = tid & 31;
    const int wid  = tid >> 5;
    const int warpRow = (wid >> 1) * 64;
    const int warpCol = (wid & 1) * 64;
    const int bm = blockIdx.y * 128;
    const int bn = blockIdx.x * 128;

    const int a_r0 = tid >> 2;
    const int a_c4 = (tid & 3) * 4;
    const int b_n4 = (tid & 31) * 4;
    const int b_k0 = tid >> 5;

    float acc[4][8][4];
    #pragma unroll
    for (int i = 0; i < 4; i++)
        #pragma unroll
        for (int j = 0; j < 8; j++)
            #pragma unroll
            for (int r = 0; r < 4; r++) acc[i][j][r] = 0.f;

    float4 pa[4], pb[4];
    const int nkt = K / TBK;

    #pragma unroll
    for (int i = 0; i < 4; i++)
        pa[i] = *(const float4*)(A + (size_t)(bm + a_r0 + 32*i) * K + a_c4);
    #pragma unroll
    for (int i = 0; i < 4; i++)
        pb[i] = *(const float4*)(B + (size_t)(b_k0 + 4*i) * N + bn + b_n4);
    #pragma unroll
    for (int i = 0; i < 4; i++) {
        const int row = a_r0 + 32*i;
        As[0][a_c4+0][row] = f2tf32(pa[i].x);
        As[0][a_c4+1][row] = f2tf32(pa[i].y);
        As[0][a_c4+2][row] = f2tf32(pa[i].z);
        As[0][a_c4+3][row] = f2tf32(pa[i].w);
    }
    #pragma unroll
    for (int i = 0; i < 4; i++) {
        uint32_t* dst = &Bs[0][b_k0 + 4*i][b_n4];
        dst[0] = f2tf32(pb[i].x);
        dst[1] = f2tf32(pb[i].y);
        dst[2] = f2tf32(pb[i].z);
        dst[3] = f2tf32(pb[i].w);
    }
    __syncthreads();

    for (int kt = 0; kt < nkt; kt++) {
        const int buf = kt & 1;

        if (kt + 1 < nkt) {
            const int k0 = (kt + 1) * TBK;
            #pragma unroll
            for (int i = 0; i < 4; i++)
                pa[i] = *(const float4*)(A + (size_t)(bm + a_r0 + 32*i) * K + k0 + a_c4);
            #pragma unroll
            for (int i = 0; i < 4; i++)
                pb[i] = *(const float4*)(B + (size_t)(k0 + b_k0 + 4*i) * N + bn + b_n4);
        }

        #pragma unroll
        for (int ks = 0; ks < 2; ks++) {
            const int kb = ks * 8;
            uint32_t af[4][4], bf[8][2];
            #pragma unroll
            for (int am = 0; am < 4; am++) {
                const int r0 = warpRow + am*16 + (lane >> 2);
                af[am][0] = As[buf][kb + (lane & 3)    ][r0];
                af[am][1] = As[buf][kb + (lane & 3)    ][r0 + 8];
                af[am][2] = As[buf][kb + (lane & 3) + 4][r0];
                af[am][3] = As[buf][kb + (lane & 3) + 4][r0 + 8];
            }
            #pragma unroll
            for (int an = 0; an < 8; an++) {
                const int c0 = warpCol + an*8 + (lane >> 2);
                bf[an][0] = Bs[buf][kb + (lane & 3)    ][c0];
                bf[an][1] = Bs[buf][kb + (lane & 3) + 4][c0];
            }
            #pragma unroll
            for (int am = 0; am < 4; am++)
                #pragma unroll
                for (int an = 0; an < 8; an++)
                    mma_tf32(acc[am][an], af[am][0], af[am][1], af[am][2], af[am][3],
                             bf[an][0], bf[an][1]);
        }

        if (kt + 1 < nkt) {
            const int nb = buf ^ 1;
            #pragma unroll
            for (int i = 0; i < 4; i++) {
                const int row = a_r0 + 32*i;
                As[nb][a_c4+0][row] = f2tf32(pa[i].x);
                As[nb][a_c4+1][row] = f2tf32(pa[i].y);
                As[nb][a_c4+2][row] = f2tf32(pa[i].z);
                As[nb][a_c4+3][row] = f2tf32(pa[i].w);
            }
            #pragma unroll
            for (int i = 0; i < 4; i++) {
                uint32_t* dst = &Bs[nb][b_k0 + 4*i][b_n4];
                dst[0] = f2tf32(pb[i].x);
                dst[1] = f2tf32(pb[i].y);
                dst[2] = f2tf32(pb[i].z);
                dst[3] = f2tf32(pb[i].w);
            }
        }
        __syncthreads();
    }

    #pragma unroll
    for (int am = 0; am < 4; am++) {
        const int r0 = bm + warpRow + am*16 + (lane >> 2);
        #pragma unroll
        for (int an = 0; an < 8; an++) {
            const int c0 = bn + warpCol + an*8 + (lane & 3)*2;
            float v0 = acc[am][an][0], v1 = acc[am][an][1];
            float v2 = acc[am][an][2], v3 = acc[am][an][3];
            if (roundC) { v0 = tf32r(v0); v1 = tf32r(v1); v2 = tf32r(v2); v3 = tf32r(v3); }
            *(float2*)(C + (size_t)r0 * N + c0)       = make_float2(v0, v1);
            *(float2*)(C + (size_t)(r0 + 8) * N + c0) = make_float2(v2, v3);
        }
    }
}

// ---------------- RoPE + gate fusion: Qcat fp32, Kcat hi/lo --------------------
__global__ void fuse_rope(const float* __restrict__ qs, const float* __restrict__ ks,
                          const float* __restrict__ qg, const float* __restrict__ kg,
                          const float* __restrict__ gate_logit,
                          const int* __restrict__ pos_offset,
                          float* __restrict__ qcat,
                          float* __restrict__ kh_o, float* __restrict__ kl_o) {
    const int row = blockIdx.x;              // (b*H + h)*T + t
    const int d   = threadIdx.x;             // 0..63
    const int t   = row % Tc;
    const int h   = (row / Tc) % Hc;
    const int b   = row / (Tc * Hc);

    const size_t src = ((size_t)(b * Tc + t)) * 1024 + h * 64 + d;
    const size_t dst = (size_t)row * 128;

    const float gate = 1.f / (1.f + __expf(-gate_logit[h]));
    const float scale = 0.125f;              // 1/sqrt(64)
    const float gq_sem = 2.f * gate * scale;
    const float gq_geo = (2.f - 2.f * gate) * scale;

    qcat[dst + d] = qs[src] * gq_sem;
    {
        const float kv = ks[src];
        const float kh = tf32r(kv);
        kh_o[dst + d] = kh;
        kl_o[dst + d] = tf32r(kv - kh);
    }

    if (d < 32) {
        const float inv_freq = powf(10000.f, -(float)d / 32.f);
        const float ang = ((float)t + (float)(*pos_offset)) * inv_freq;
        const float c = cosf(ang), s = sinf(ang);
        const float q1 = qg[src], q2 = qg[src + 32];
        const float k1 = kg[src], k2 = kg[src + 32];
        qcat[dst + 64 + d]      = (q1 * c - q2 * s) * gq_geo;
        qcat[dst + 64 + d + 32] = (q2 * c + q1 * s) * gq_geo;
        const float ka = k1 * c - k2 * s;
        const float kb = k2 * c + k1 * s;
        const float kah = tf32r(ka), kbh = tf32r(kb);
        kh_o[dst + 64 + d]      = kah;
        kl_o[dst + 64 + d]      = tf32r(ka - kah);
        kh_o[dst + 64 + d + 32] = kbh;
        kl_o[dst + 64 + d + 32] = tf32r(kb - kbh);
    }
}

// ---------------- Flash attention v4 -------------------------------------------
// BM=128 (8 warps x 16 rows), BN=64. 3xTF32 QK, plain tf32 PV.
// cp.async double-buffered K(hi/lo)+V tiles; P stays in registers (frag shuffle).
#define F4_KSTR 132
#define F4_VSTR 136
#define F4_KBUF (64*F4_KSTR)      // floats per K buffer
#define F4_VBUF (64*F4_VSTR)
#define F4_SMEM_FLOATS (4*F4_KBUF + 2*F4_VBUF)
#define F4_SMEM_BYTES  (F4_SMEM_FLOATS * 4)   // 204800 B

__global__ __launch_bounds__(256, 1) void flash4(
    const float* __restrict__ Qc,
    const float* __restrict__ Khg, const float* __restrict__ Klg,
    const float* __restrict__ Vtg,
    float* __restrict__ Out)
{
    extern __shared__ float sm[];
    float* sKh = sm;                     // [2][64][132]
    float* sKl = sm + 2*F4_KBUF;         // [2][64][132]
    float* sVh = sm + 4*F4_KBUF;         // [2][64][136]

    const int qb = gridDim.x - 1 - blockIdx.x;   // heavy CTAs first
    const int bh = blockIdx.y;
    const int b  = bh >> 4, h = bh & 15;
    const int tid  = threadIdx.x;
    const int lane = tid & 31;
    const int wid  = tid >> 5;
    const int g = lane >> 2;
    const int t = lane & 3;
    const int r0 = wid * 16 + g;

    const float* Qg   = Qc  + ((size_t)bh * Tc + qb * 128) * 128;
    const float* Kh_p = Khg + (size_t)bh * Tc * 128;
    const float* Kl_p = Klg + (size_t)bh * Tc * 128;
    const float* Vh_p = Vtg + (size_t)b * Tc * 2048 + h * 128;

    // ---- stage Q through smem (Kh region = 128x132), pull to registers ----
    for (int i = tid; i < 4096; i += 256) {
        const int r = i >> 5, c4 = (i & 31) << 2;
        *(float4*)&sKh[r * F4_KSTR + c4] = *(const float4*)(Qg + r * 128 + c4);
    }
    __syncthreads();
    float qf[16][4];
    #pragma unroll
    for (int ks = 0; ks < 16; ks++) {
        qf[ks][0] = sKh[ r0      * F4_KSTR + ks*8 + t];
        qf[ks][1] = sKh[(r0 + 8) * F4_KSTR + ks*8 + t];
        qf[ks][2] = sKh[ r0      * F4_KSTR + ks*8 + t + 4];
        qf[ks][3] = sKh[(r0 + 8) * F4_KSTR + ks*8 + t + 4];
    }
    __syncthreads();    // all reads done before cp.async overwrites

    const int ntiles = 2 * qb + 2;

    // ---- prologue: prefetch tiles 0 and 1 ----
    #pragma unroll
    for (int pre = 0; pre < 2; pre++) {
        float* dKh = sKh + pre * F4_KBUF;
        float* dKl = sKl + pre * F4_KBUF;
        float* dVh = sVh + pre * F4_VBUF;
        #pragma unroll
        for (int j = 0; j < 8; j++) {
            const int i = tid + j * 256;
            const int r = i >> 5, c4 = (i & 31) << 2;
            const size_t krow = (size_t)(pre * 64 + r);
            cp16(&dKh[r*F4_KSTR + c4], Kh_p + krow*128  + c4);
            cp16(&dKl[r*F4_KSTR + c4], Kl_p + krow*128  + c4);
            cp16(&dVh[r*F4_VSTR + c4], Vh_p + krow*2048 + c4);
        }
        cp_commit();
    }

    float oreg[16][4];
    #pragma unroll
    for (int n = 0; n < 16; n++) {
        oreg[n][0] = 0.f; oreg[n][1] = 0.f; oreg[n][2] = 0.f; oreg[n][3] = 0.f;
    }
    float M0 = -1e30f, M1 = -1e30f, L0 = 0.f, L1 = 0.f;

    const int srcA = (lane & 28) | (t >> 1);
    const int srcB = srcA + 2;
    const bool odd = (t & 1);

    for (int kt = 0; kt < ntiles; kt++) {
        const int buf = kt & 1;
        const uint32_t* uKh = (const uint32_t*)(sKh + buf * F4_KBUF);
        const uint32_t* uKl = (const uint32_t*)(sKl + buf * F4_KBUF);
        const uint32_t* uVh = (const uint32_t*)(sVh + buf * F4_VBUF);

        if (kt + 1 < ntiles) cp_wait1(); else cp_wait0();
        __syncthreads();

        // ---- S = Q K^T (3xTF32), 8 n-atoms per warp ----
        float sreg[8][4];
        #pragma unroll
        for (int n = 0; n < 8; n++) {
            sreg[n][0] = 0.f; sreg[n][1] = 0.f; sreg[n][2] = 0.f; sreg[n][3] = 0.f;
        }
        #pragma unroll
        for (int ks = 0; ks < 16; ks++) {
            uint32_t ah[4], al[4];
            #pragma unroll
            for (int e = 0; e < 4; e++) {
                ah[e] = f2tf32(qf[ks][e]);
                al[e] = f2tf32(qf[ks][e] - __uint_as_float(ah[e]));
            }
            const int kb = ks*8 + t;
            #pragma unroll
            for (int n = 0; n < 8; n++) {
                const int kr = n*8 + g;
                const uint32_t bh0 = uKh[kr*F4_KSTR + kb], bh1 = uKh[kr*F4_KSTR + kb + 4];
                const uint32_t bl0 = uKl[kr*F4_KSTR + kb], bl1 = uKl[kr*F4_KSTR + kb + 4];
                mma_tf32(sreg[n], ah[0], ah[1], ah[2], ah[3], bh0, bh1);
                mma_tf32(sreg[n], al[0], al[1], al[2], al[3], bh0, bh1);
                mma_tf32(sreg[n], ah[0], ah[1], ah[2], ah[3], bl0, bl1);
            }
        }

        // ---- causal mask ----
        if (kt >= 2 * qb) {
            const int qrow0 = qb * 128 + r0;
            const int qrow1 = qrow0 + 8;
            #pragma unroll
            for (int n = 0; n < 8; n++) {
                const int c = kt * 64 + n*8 + 2*t;
                if (c     > qrow0) sreg[n][0] = -1e30f;
                if (c + 1 > qrow0) sreg[n][1] = -1e30f;
                if (c     > qrow1) sreg[n][2] = -1e30f;
                if (c + 1 > qrow1) sreg[n][3] = -1e30f;
            }
        }

        // ---- online softmax (rows r0, r0+8; reduce over quad) ----
        float mx0 = -1e30f, mx1 = -1e30f;
        #pragma unroll
        for (int n = 0; n < 8; n++) {
            mx0 = fmaxf(mx0, fmaxf(sreg[n][0], sreg[n][1]));
            mx1 = fmaxf(mx1, fmaxf(sreg[n][2], sreg[n][3]));
        }
        mx0 = fmaxf(mx0, __shfl_xor_sync(0xffffffffu, mx0, 1));
        mx0 = fmaxf(mx0, __shfl_xor_sync(0xffffffffu, mx0, 2));
        mx1 = fmaxf(mx1, __shfl_xor_sync(0xffffffffu, mx1, 1));
        mx1 = fmaxf(mx1, __shfl_xor_sync(0xffffffffu, mx1, 2));
        const float mn0 = fmaxf(M0, mx0), mn1 = fmaxf(M1, mx1);
        const float sc0 = __expf(M0 - mn0), sc1 = __expf(M1 - mn1);
        float sum0 = 0.f, sum1 = 0.f;
        #pragma unroll
        for (int n = 0; n < 8; n++) {
            sreg[n][0] = __expf(sreg[n][0] - mn0); sum0 += sreg[n][0];
            sreg[n][1] = __expf(sreg[n][1] - mn0); sum0 += sreg[n][1];
            sreg[n][2] = __expf(sreg[n][2] - mn1); sum1 += sreg[n][2];
            sreg[n][3] = __expf(sreg[n][3] - mn1); sum1 += sreg[n][3];
        }
        sum0 += __shfl_xor_sync(0xffffffffu, sum0, 1);
        sum0 += __shfl_xor_sync(0xffffffffu, sum0, 2);
        sum1 += __shfl_xor_sync(0xffffffffu, sum1, 1);
        sum1 += __shfl_xor_sync(0xffffffffu, sum1, 2);
        M0 = mn0; M1 = mn1;
        L0 = L0 * sc0 + sum0;
        L1 = L1 * sc1 + sum1;
        #pragma unroll
        for (int n = 0; n < 16; n++) {
            oreg[n][0] *= sc0; oreg[n][1] *= sc0;
            oreg[n][2] *= sc1; oreg[n][3] *= sc1;
        }

        // ---- O += P V (plain tf32); P converted C-frag -> A-frag via shuffles --
        #pragma unroll
        for (int ka = 0; ka < 8; ka++) {
            const float v00 = sreg[ka][0], v01 = sreg[ka][1];
            const float v10 = sreg[ka][2], v11 = sreg[ka][3];
            float w0 = __shfl_sync(0xffffffffu, v00, srcA);
            float w1 = __shfl_sync(0xffffffffu, v01, srcA);
            float w2 = __shfl_sync(0xffffffffu, v10, srcA);
            float w3 = __shfl_sync(0xffffffffu, v11, srcA);
            float w4 = __shfl_sync(0xffffffffu, v00, srcB);
            float w5 = __shfl_sync(0xffffffffu, v01, srcB);
            float w6 = __shfl_sync(0xffffffffu, v10, srcB);
            float w7 = __shfl_sync(0xffffffffu, v11, srcB);
            const uint32_t a0 = f2tf32(odd ? w1 : w0);
            const uint32_t a1 = f2tf32(odd ? w3 : w2);
            const uint32_t a2 = f2tf32(odd ? w5 : w4);
            const uint32_t a3 = f2tf32(odd ? w7 : w6);
            const int kr0 = (ka*8 + t) * F4_VSTR;
            const int kr1 = (ka*8 + t + 4) * F4_VSTR;
            #pragma unroll
            for (int n = 0; n < 16; n++) {
                const int vc = n*8 + g;
                mma_tf32(oreg[n], a0, a1, a2, a3, uVh[kr0 + vc], uVh[kr1 + vc]);
            }
        }

        __syncthreads();   // all warps done reading buf before refill

        // ---- prefetch tile kt+2 into this buffer ----
        if (kt + 2 < ntiles) {
            float* dKh = sKh + buf * F4_KBUF;
            float* dKl = sKl + buf * F4_KBUF;
            float* dVh = sVh + buf * F4_VBUF;
            #pragma unroll
            for (int j = 0; j < 8; j++) {
                const int i = tid + j * 256;
                const int r = i >> 5, c4 = (i & 31) << 2;
                const size_t krow = (size_t)((kt + 2) * 64 + r);
                cp16(&dKh[r*F4_KSTR + c4], Kh_p + krow*128  + c4);
                cp16(&dKl[r*F4_KSTR + c4], Kl_p + krow*128  + c4);
                cp16(&dVh[r*F4_VSTR + c4], Vh_p + krow*2048 + c4);
            }
            cp_commit();
        }
    }

    // ---- epilogue ----
    const float inv0 = 1.f / L0, inv1 = 1.f / L1;
    const size_t row0 = (size_t)b * Tc + qb * 128 + r0;
    #pragma unroll
    for (int n = 0; n < 16; n++) {
        const int col = h * 128 + n*8 + 2*t;
        *(float2*)(Out +  row0      * 2048 + col) = make_float2(oreg[n][0]*inv0, oreg[n][1]*inv0);
        *(float2*)(Out + (row0 + 8) * 2048 + col) = make_float2(oreg[n][2]*inv1, oreg[n][3]*inv1);
    }
}

// ---------------- host launch --------------------------------------------------
extern "C" void kernel_launch(void* const* d_in, const int* in_sizes, int n_in,
                              void* d_out, int out_size) {
    const float* x          = (const float*)d_in[0];
    const float* Wq_sem     = (const float*)d_in[1];
    const float* Wk_sem     = (const float*)d_in[2];
    const float* Wq_geo     = (const float*)d_in[3];
    const float* Wk_geo     = (const float*)d_in[4];
    const float* Wv         = (const float*)d_in[5];
    const float* Wo         = (const float*)d_in[6];
    const float* gate_logit = (const float*)d_in[7];
    const int*   pos_offset = (const int*)d_in[8];
    float* out = (float*)d_out;

    float *qs, *ks, *qg, *kg, *vt, *qcat, *kh, *kl, *ao;
    cudaGetSymbolAddress((void**)&qs,   g_qs);
    cudaGetSymbolAddress((void**)&ks,   g_ks);
    cudaGetSymbolAddress((void**)&qg,   g_qg);
    cudaGetSymbolAddress((void**)&kg,   g_kg);
    cudaGetSymbolAddress((void**)&vt,   g_vt);
    cudaGetSymbolAddress((void**)&qcat, g_qcat);
    cudaGetSymbolAddress((void**)&kh,   g_kh);
    cudaGetSymbolAddress((void**)&kl,   g_kl);
    cudaGetSymbolAddress((void**)&ao,   g_ao);

    const dim3 blk(128);

    // projections (tf32 tensor cores); V rounded to tf32 in epilogue
    gemm_tf32<<<dim3(1024/128, MROWS/128), blk>>>(x, Wq_sem, qs, MROWS, 1024, 2048, 0);
    gemm_tf32<<<dim3(1024/128, MROWS/128), blk>>>(x, Wk_sem, ks, MROWS, 1024, 2048, 0);
    gemm_tf32<<<dim3(1024/128, MROWS/128), blk>>>(x, Wq_geo, qg, MROWS, 1024, 2048, 0);
    gemm_tf32<<<dim3(1024/128, MROWS/128), blk>>>(x, Wk_geo, kg, MROWS, 1024, 2048, 0);
    gemm_tf32<<<dim3(2048/128, MROWS/128), blk>>>(x, Wv,     vt, MROWS, 2048, 2048, 1);

    // RoPE + gate + scale fusion; K emitted as tf32 hi/lo
    fuse_rope<<<Bc * Hc * Tc, 64>>>(qs, ks, qg, kg, gate_logit, pos_offset,
                                    qcat, kh, kl);

    // flash attention (causal), pipelined tensor-core version
    cudaFuncSetAttribute(flash4, cudaFuncAttributeMaxDynamicSharedMemorySize,
                         F4_SMEM_BYTES);
    flash4<<<dim3(Tc / 128, Bc * Hc), 256, F4_SMEM_BYTES>>>(qcat, kh, kl, vt, ao);

    // output projection (tf32 tensor cores)
    gemm_tf32<<<dim3(2048/128, MROWS/128), blk>>>(ao, Wo, out, MROWS, 2048, 2048, 0);
}

// round 6
// speedup vs baseline: 4.0089x; 1.0830x over previous
#include <cuda_runtime.h>
#include <math.h>
#include <stdint.h>

// Problem constants
#define Bc 2
#define Tc 2048
#define Dc 2048
#define Hc 16
#define MROWS (Bc*Tc)          // 4096

// ---------------- scratch (device globals; no allocation allowed) -------------
__device__ float g_qs[MROWS * 1024];
__device__ float g_ks[MROWS * 1024];
__device__ float g_qg[MROWS * 1024];
__device__ float g_kg[MROWS * 1024];
__device__ float g_vt[MROWS * 2048];           // V, tf32-rounded
__device__ float g_qcat[Bc*Hc*Tc*128];
__device__ float g_kt  [Bc*Hc*Tc*128];         // K, tf32-rounded
__device__ float g_ao [MROWS * 2048];

// ---------------- tf32 helpers -------------------------------------------------
__device__ __forceinline__ uint32_t f2tf32(float f) {
    uint32_t u;
    asm("cvt.rna.tf32.f32 %0, %1;" : "=r"(u) : "f"(f));
    return u;
}
__device__ __forceinline__ float tf32r(float x) {
    return __uint_as_float(f2tf32(x));
}

__device__ __forceinline__ void mma_tf32(float* c,
                                         uint32_t a0, uint32_t a1, uint32_t a2, uint32_t a3,
                                         uint32_t b0, uint32_t b1) {
    asm volatile("mma.sync.aligned.m16n8k8.row.col.f32.tf32.tf32.f32 "
                 "{%0,%1,%2,%3}, {%4,%5,%6,%7}, {%8,%9}, {%0,%1,%2,%3};"
                 : "+f"(c[0]), "+f"(c[1]), "+f"(c[2]), "+f"(c[3])
                 : "r"(a0), "r"(a1), "r"(a2), "r"(a3), "r"(b0), "r"(b1));
}

__device__ __forceinline__ void cp16(void* dst, const void* src) {
    uint32_t d = (uint32_t)__cvta_generic_to_shared(dst);
    asm volatile("cp.async.cg.shared.global [%0], [%1], 16;" :: "r"(d), "l"(src));
}
__device__ __forceinline__ void cp_commit() {
    asm volatile("cp.async.commit_group;");
}
__device__ __forceinline__ void cp_wait1() {
    asm volatile("cp.async.wait_group 1;");
}
__device__ __forceinline__ void cp_wait0() {
    asm volatile("cp.async.wait_group 0;");
}

// ---------------- tf32 tensor-core GEMM: C[M,N] = A[M,K] @ B[K,N] --------------
#define TBK 16

__global__ __launch_bounds__(128, 2) void gemm_tf32(const float* __restrict__ A,
                                                    const float* __restrict__ B,
                                                    float* __restrict__ C,
                                                    int M, int N, int K, int roundC) {
    __shared__ uint32_t As[2][TBK][132];
    __shared__ uint32_t Bs[2][TBK][136];

    const int tid  = threadIdx.x;
    const int lane = tid & 31;
    const int wid  = tid >> 5;
    const int warpRow = (wid >> 1) * 64;
    const int warpCol = (wid & 1) * 64;
    const int bm = blockIdx.y * 128;
    const int bn = blockIdx.x * 128;

    const int a_r0 = tid >> 2;
    const int a_c4 = (tid & 3) * 4;
    const int b_n4 = (tid & 31) * 4;
    const int b_k0 = tid >> 5;

    float acc[4][8][4];
    #pragma unroll
    for (int i = 0; i < 4; i++)
        #pragma unroll
        for (int j = 0; j < 8; j++)
            #pragma unroll
            for (int r = 0; r < 4; r++) acc[i][j][r] = 0.f;

    float4 pa[4], pb[4];
    const int nkt = K / TBK;

    #pragma unroll
    for (int i = 0; i < 4; i++)
        pa[i] = *(const float4*)(A + (size_t)(bm + a_r0 + 32*i) * K + a_c4);
    #pragma unroll
    for (int i = 0; i < 4; i++)
        pb[i] = *(const float4*)(B + (size_t)(b_k0 + 4*i) * N + bn + b_n4);
    #pragma unroll
    for (int i = 0; i < 4; i++) {
        const int row = a_r0 + 32*i;
        As[0][a_c4+0][row] = f2tf32(pa[i].x);
        As[0][a_c4+1][row] = f2tf32(pa[i].y);
        As[0][a_c4+2][row] = f2tf32(pa[i].z);
        As[0][a_c4+3][row] = f2tf32(pa[i].w);
    }
    #pragma unroll
    for (int i = 0; i < 4; i++) {
        uint32_t* dst = &Bs[0][b_k0 + 4*i][b_n4];
        dst[0] = f2tf32(pb[i].x);
        dst[1] = f2tf32(pb[i].y);
        dst[2] = f2tf32(pb[i].z);
        dst[3] = f2tf32(pb[i].w);
    }
    __syncthreads();

    for (int kt = 0; kt < nkt; kt++) {
        const int buf = kt & 1;

        if (kt + 1 < nkt) {
            const int k0 = (kt + 1) * TBK;
            #pragma unroll
            for (int i = 0; i < 4; i++)
                pa[i] = *(const float4*)(A + (size_t)(bm + a_r0 + 32*i) * K + k0 + a_c4);
            #pragma unroll
            for (int i = 0; i < 4; i++)
                pb[i] = *(const float4*)(B + (size_t)(k0 + b_k0 + 4*i) * N + bn + b_n4);
        }

        #pragma unroll
        for (int ks = 0; ks < 2; ks++) {
            const int kb = ks * 8;
            uint32_t af[4][4], bf[8][2];
            #pragma unroll
            for (int am = 0; am < 4; am++) {
                const int r0 = warpRow + am*16 + (lane >> 2);
                af[am][0] = As[buf][kb + (lane & 3)    ][r0];
                af[am][1] = As[buf][kb + (lane & 3)    ][r0 + 8];
                af[am][2] = As[buf][kb + (lane & 3) + 4][r0];
                af[am][3] = As[buf][kb + (lane & 3) + 4][r0 + 8];
            }
            #pragma unroll
            for (int an = 0; an < 8; an++) {
                const int c0 = warpCol + an*8 + (lane >> 2);
                bf[an][0] = Bs[buf][kb + (lane & 3)    ][c0];
                bf[an][1] = Bs[buf][kb + (lane & 3) + 4][c0];
            }
            #pragma unroll
            for (int am = 0; am < 4; am++)
                #pragma unroll
                for (int an = 0; an < 8; an++)
                    mma_tf32(acc[am][an], af[am][0], af[am][1], af[am][2], af[am][3],
                             bf[an][0], bf[an][1]);
        }

        if (kt + 1 < nkt) {
            const int nb = buf ^ 1;
            #pragma unroll
            for (int i = 0; i < 4; i++) {
                const int row = a_r0 + 32*i;
                As[nb][a_c4+0][row] = f2tf32(pa[i].x);
                As[nb][a_c4+1][row] = f2tf32(pa[i].y);
                As[nb][a_c4+2][row] = f2tf32(pa[i].z);
                As[nb][a_c4+3][row] = f2tf32(pa[i].w);
            }
            #pragma unroll
            for (int i = 0; i < 4; i++) {
                uint32_t* dst = &Bs[nb][b_k0 + 4*i][b_n4];
                dst[0] = f2tf32(pb[i].x);
                dst[1] = f2tf32(pb[i].y);
                dst[2] = f2tf32(pb[i].z);
                dst[3] = f2tf32(pb[i].w);
            }
        }
        __syncthreads();
    }

    #pragma unroll
    for (int am = 0; am < 4; am++) {
        const int r0 = bm + warpRow + am*16 + (lane >> 2);
        #pragma unroll
        for (int an = 0; an < 8; an++) {
            const int c0 = bn + warpCol + an*8 + (lane & 3)*2;
            float v0 = acc[am][an][0], v1 = acc[am][an][1];
            float v2 = acc[am][an][2], v3 = acc[am][an][3];
            if (roundC) { v0 = tf32r(v0); v1 = tf32r(v1); v2 = tf32r(v2); v3 = tf32r(v3); }
            *(float2*)(C + (size_t)r0 * N + c0)       = make_float2(v0, v1);
            *(float2*)(C + (size_t)(r0 + 8) * N + c0) = make_float2(v2, v3);
        }
    }
}

// ---------------- RoPE + gate fusion: Qcat fp32, K tf32-rounded ----------------
__global__ void fuse_rope(const float* __restrict__ qs, const float* __restrict__ ks,
                          const float* __restrict__ qg, const float* __restrict__ kg,
                          const float* __restrict__ gate_logit,
                          const int* __restrict__ pos_offset,
                          float* __restrict__ qcat, float* __restrict__ kt_o) {
    const int row = blockIdx.x;              // (b*H + h)*T + t
    const int d   = threadIdx.x;             // 0..63
    const int t   = row % Tc;
    const int h   = (row / Tc) % Hc;
    const int b   = row / (Tc * Hc);

    const size_t src = ((size_t)(b * Tc + t)) * 1024 + h * 64 + d;
    const size_t dst = (size_t)row * 128;

    const float gate = 1.f / (1.f + __expf(-gate_logit[h]));
    const float scale = 0.125f;              // 1/sqrt(64)
    const float gq_sem = 2.f * gate * scale;
    const float gq_geo = (2.f - 2.f * gate) * scale;

    qcat[dst + d] = qs[src] * gq_sem;
    kt_o[dst + d] = tf32r(ks[src]);

    if (d < 32) {
        const float inv_freq = powf(10000.f, -(float)d / 32.f);
        const float ang = ((float)t + (float)(*pos_offset)) * inv_freq;
        const float c = cosf(ang), s = sinf(ang);
        const float q1 = qg[src], q2 = qg[src + 32];
        const float k1 = kg[src], k2 = kg[src + 32];
        qcat[dst + 64 + d]      = (q1 * c - q2 * s) * gq_geo;
        qcat[dst + 64 + d + 32] = (q2 * c + q1 * s) * gq_geo;
        kt_o[dst + 64 + d]      = tf32r(k1 * c - k2 * s);
        kt_o[dst + 64 + d + 32] = tf32r(k2 * c + k1 * s);
    }
}

// ---------------- Flash attention v5 -------------------------------------------
// BM=128 (8 warps x 16 rows), BN=64. 2-term QK (Q hi/lo, K tf32), tf32 PV.
// 3-stage cp.async ring; ONE __syncthreads per tile; P in registers.
#define F5_KSTR 132
#define F5_VSTR 136
#define F5_KBUF (64*F5_KSTR)
#define F5_VBUF (64*F5_VSTR)
#define F5_STAGE (F5_KBUF + F5_VBUF)
#define F5_SMEM_FLOATS (3 * F5_STAGE)
#define F5_SMEM_BYTES  (F5_SMEM_FLOATS * 4)   // 205,824 B

__global__ __launch_bounds__(256, 1) void flash5(
    const float* __restrict__ Qc,
    const float* __restrict__ Ktg,
    const float* __restrict__ Vtg,
    float* __restrict__ Out)
{
    extern __shared__ float sm[];

    const int qb = gridDim.x - 1 - blockIdx.x;   // heavy CTAs first
    const int bh = blockIdx.y;
    const int b  = bh >> 4, h = bh & 15;
    const int tid  = threadIdx.x;
    const int lane = tid & 31;
    const int wid  = tid >> 5;
    const int g = lane >> 2;
    const int t = lane & 3;
    const int r0 = wid * 16 + g;

    const float* Qg  = Qc  + ((size_t)bh * Tc + qb * 128) * 128;
    const float* Kp  = Ktg + (size_t)bh * Tc * 128;
    const float* Vp  = Vtg + (size_t)b * Tc * 2048 + h * 128;

    // ---- stage Q through stage-0 region, pull fp32 to registers ----
    for (int i = tid; i < 4096; i += 256) {
        const int r = i >> 5, c4 = (i & 31) << 2;
        *(float4*)&sm[r * F5_KSTR + c4] = *(const float4*)(Qg + r * 128 + c4);
    }
    __syncthreads();
    float qf[16][4];
    #pragma unroll
    for (int ks = 0; ks < 16; ks++) {
        qf[ks][0] = sm[ r0      * F5_KSTR + ks*8 + t];
        qf[ks][1] = sm[(r0 + 8) * F5_KSTR + ks*8 + t];
        qf[ks][2] = sm[ r0      * F5_KSTR + ks*8 + t + 4];
        qf[ks][3] = sm[(r0 + 8) * F5_KSTR + ks*8 + t + 4];
    }
    __syncthreads();    // reads done before prefetch overwrites

    const int ntiles = 2 * qb + 2;

    // ---- prologue: prefetch tiles 0, 1 into stages 0, 1 ----
    #pragma unroll
    for (int pre = 0; pre < 2; pre++) {
        float* dK = sm + pre * F5_STAGE;
        float* dV = dK + F5_KBUF;
        #pragma unroll
        for (int j = 0; j < 8; j++) {
            const int i = tid + j * 256;
            const int r = i >> 5, c4 = (i & 31) << 2;
            const size_t krow = (size_t)(pre * 64 + r);
            cp16(&dK[r*F5_KSTR + c4], Kp + krow*128  + c4);
            cp16(&dV[r*F5_VSTR + c4], Vp + krow*2048 + c4);
        }
        cp_commit();
    }

    float oreg[16][4];
    #pragma unroll
    for (int n = 0; n < 16; n++) {
        oreg[n][0] = 0.f; oreg[n][1] = 0.f; oreg[n][2] = 0.f; oreg[n][3] = 0.f;
    }
    float M0 = -1e30f, M1 = -1e30f, L0 = 0.f, L1 = 0.f;

    const int srcA = (lane & 28) | (t >> 1);
    const int srcB = srcA + 2;
    const bool odd = (t & 1);

    int s_cur = 0, s_pre = 2;     // stage of tile kt ; stage for tile kt+2
    for (int kt = 0; kt < ntiles; kt++) {
        // tile kt's data arrival (this thread's groups), then publish to all
        if (kt + 1 < ntiles) cp_wait1(); else cp_wait0();
        __syncthreads();   // single barrier: kt data visible; stage s_pre free

        // ---- prefetch tile kt+2 ----
        if (kt + 2 < ntiles) {
            float* dK = sm + s_pre * F5_STAGE;
            float* dV = dK + F5_KBUF;
            #pragma unroll
            for (int j = 0; j < 8; j++) {
                const int i = tid + j * 256;
                const int r = i >> 5, c4 = (i & 31) << 2;
                const size_t krow = (size_t)((kt + 2) * 64 + r);
                cp16(&dK[r*F5_KSTR + c4], Kp + krow*128  + c4);
                cp16(&dV[r*F5_VSTR + c4], Vp + krow*2048 + c4);
            }
            cp_commit();
        }

        const uint32_t* uK = (const uint32_t*)(sm + s_cur * F5_STAGE);
        const uint32_t* uV = uK + F5_KBUF;

        // ---- S = Q K^T (2-term: Qhi + Qlo, K rounded), 8 n-atoms/warp ----
        float sreg[8][4];
        #pragma unroll
        for (int n = 0; n < 8; n++) {
            sreg[n][0] = 0.f; sreg[n][1] = 0.f; sreg[n][2] = 0.f; sreg[n][3] = 0.f;
        }
        #pragma unroll
        for (int ks = 0; ks < 16; ks++) {
            uint32_t ah[4], al[4];
            #pragma unroll
            for (int e = 0; e < 4; e++) {
                ah[e] = f2tf32(qf[ks][e]);
                al[e] = f2tf32(qf[ks][e] - __uint_as_float(ah[e]));
            }
            const int kb = ks*8 + t;
            #pragma unroll
            for (int n = 0; n < 8; n++) {
                const int kr = n*8 + g;
                const uint32_t bh0 = uK[kr*F5_KSTR + kb], bh1 = uK[kr*F5_KSTR + kb + 4];
                mma_tf32(sreg[n], ah[0], ah[1], ah[2], ah[3], bh0, bh1);
                mma_tf32(sreg[n], al[0], al[1], al[2], al[3], bh0, bh1);
            }
        }

        // ---- causal mask ----
        if (kt >= 2 * qb) {
            const int qrow0 = qb * 128 + r0;
            const int qrow1 = qrow0 + 8;
            #pragma unroll
            for (int n = 0; n < 8; n++) {
                const int c = kt * 64 + n*8 + 2*t;
                if (c     > qrow0) sreg[n][0] = -1e30f;
                if (c + 1 > qrow0) sreg[n][1] = -1e30f;
                if (c     > qrow1) sreg[n][2] = -1e30f;
                if (c + 1 > qrow1) sreg[n][3] = -1e30f;
            }
        }

        // ---- online softmax (rows r0, r0+8; quad reduction) ----
        float mx0 = -1e30f, mx1 = -1e30f;
        #pragma unroll
        for (int n = 0; n < 8; n++) {
            mx0 = fmaxf(mx0, fmaxf(sreg[n][0], sreg[n][1]));
            mx1 = fmaxf(mx1, fmaxf(sreg[n][2], sreg[n][3]));
        }
        mx0 = fmaxf(mx0, __shfl_xor_sync(0xffffffffu, mx0, 1));
        mx0 = fmaxf(mx0, __shfl_xor_sync(0xffffffffu, mx0, 2));
        mx1 = fmaxf(mx1, __shfl_xor_sync(0xffffffffu, mx1, 1));
        mx1 = fmaxf(mx1, __shfl_xor_sync(0xffffffffu, mx1, 2));
        const float mn0 = fmaxf(M0, mx0), mn1 = fmaxf(M1, mx1);
        const float sc0 = __expf(M0 - mn0), sc1 = __expf(M1 - mn1);
        float sum0 = 0.f, sum1 = 0.f;
        #pragma unroll
        for (int n = 0; n < 8; n++) {
            sreg[n][0] = __expf(sreg[n][0] - mn0); sum0 += sreg[n][0];
            sreg[n][1] = __expf(sreg[n][1] - mn0); sum0 += sreg[n][1];
            sreg[n][2] = __expf(sreg[n][2] - mn1); sum1 += sreg[n][2];
            sreg[n][3] = __expf(sreg[n][3] - mn1); sum1 += sreg[n][3];
        }
        sum0 += __shfl_xor_sync(0xffffffffu, sum0, 1);
        sum0 += __shfl_xor_sync(0xffffffffu, sum0, 2);
        sum1 += __shfl_xor_sync(0xffffffffu, sum1, 1);
        sum1 += __shfl_xor_sync(0xffffffffu, sum1, 2);
        M0 = mn0; M1 = mn1;
        L0 = L0 * sc0 + sum0;
        L1 = L1 * sc1 + sum1;
        #pragma unroll
        for (int n = 0; n < 16; n++) {
            oreg[n][0] *= sc0; oreg[n][1] *= sc0;
            oreg[n][2] *= sc1; oreg[n][3] *= sc1;
        }

        // ---- O += P V (tf32); P C-frag -> A-frag via shuffles ----
        #pragma unroll
        for (int ka = 0; ka < 8; ka++) {
            const float v00 = sreg[ka][0], v01 = sreg[ka][1];
            const float v10 = sreg[ka][2], v11 = sreg[ka][3];
            float w0 = __shfl_sync(0xffffffffu, v00, srcA);
            float w1 = __shfl_sync(0xffffffffu, v01, srcA);
            float w2 = __shfl_sync(0xffffffffu, v10, srcA);
            float w3 = __shfl_sync(0xffffffffu, v11, srcA);
            float w4 = __shfl_sync(0xffffffffu, v00, srcB);
            float w5 = __shfl_sync(0xffffffffu, v01, srcB);
            float w6 = __shfl_sync(0xffffffffu, v10, srcB);
            float w7 = __shfl_sync(0xffffffffu, v11, srcB);
            const uint32_t a0 = f2tf32(odd ? w1 : w0);
            const uint32_t a1 = f2tf32(odd ? w3 : w2);
            const uint32_t a2 = f2tf32(odd ? w5 : w4);
            const uint32_t a3 = f2tf32(odd ? w7 : w6);
            const int kr0 = (ka*8 + t) * F5_VSTR;
            const int kr1 = (ka*8 + t + 4) * F5_VSTR;
            #pragma unroll
            for (int n = 0; n < 16; n++) {
                const int vc = n*8 + g;
                mma_tf32(oreg[n], a0, a1, a2, a3, uV[kr0 + vc], uV[kr1 + vc]);
            }
        }

        // rotate stages
        s_cur = (s_cur == 2) ? 0 : s_cur + 1;
        s_pre = (s_pre == 2) ? 0 : s_pre + 1;
    }

    // ---- epilogue ----
    const float inv0 = 1.f / L0, inv1 = 1.f / L1;
    const size_t row0 = (size_t)b * Tc + qb * 128 + r0;
    #pragma unroll
    for (int n = 0; n < 16; n++) {
        const int col = h * 128 + n*8 + 2*t;
        *(float2*)(Out +  row0      * 2048 + col) = make_float2(oreg[n][0]*inv0, oreg[n][1]*inv0);
        *(float2*)(Out + (row0 + 8) * 2048 + col) = make_float2(oreg[n][2]*inv1, oreg[n][3]*inv1);
    }
}

// ---------------- host launch --------------------------------------------------
extern "C" void kernel_launch(void* const* d_in, const int* in_sizes, int n_in,
                              void* d_out, int out_size) {
    const float* x          = (const float*)d_in[0];
    const float* Wq_sem     = (const float*)d_in[1];
    const float* Wk_sem     = (const float*)d_in[2];
    const float* Wq_geo     = (const float*)d_in[3];
    const float* Wk_geo     = (const float*)d_in[4];
    const float* Wv         = (const float*)d_in[5];
    const float* Wo         = (const float*)d_in[6];
    const float* gate_logit = (const float*)d_in[7];
    const int*   pos_offset = (const int*)d_in[8];
    float* out = (float*)d_out;

    float *qs, *ks, *qg, *kg, *vt, *qcat, *kt, *ao;
    cudaGetSymbolAddress((void**)&qs,   g_qs);
    cudaGetSymbolAddress((void**)&ks,   g_ks);
    cudaGetSymbolAddress((void**)&qg,   g_qg);
    cudaGetSymbolAddress((void**)&kg,   g_kg);
    cudaGetSymbolAddress((void**)&vt,   g_vt);
    cudaGetSymbolAddress((void**)&qcat, g_qcat);
    cudaGetSymbolAddress((void**)&kt,   g_kt);
    cudaGetSymbolAddress((void**)&ao,   g_ao);

    const dim3 blk(128);

    // projections (tf32 tensor cores); V rounded to tf32 in epilogue
    gemm_tf32<<<dim3(1024/128, MROWS/128), blk>>>(x, Wq_sem, qs, MROWS, 1024, 2048, 0);
    gemm_tf32<<<dim3(1024/128, MROWS/128), blk>>>(x, Wk_sem, ks, MROWS, 1024, 2048, 0);
    gemm_tf32<<<dim3(1024/128, MROWS/128), blk>>>(x, Wq_geo, qg, MROWS, 1024, 2048, 0);
    gemm_tf32<<<dim3(1024/128, MROWS/128), blk>>>(x, Wk_geo, kg, MROWS, 1024, 2048, 0);
    gemm_tf32<<<dim3(2048/128, MROWS/128), blk>>>(x, Wv,     vt, MROWS, 2048, 2048, 1);

    // RoPE + gate + scale fusion; K emitted tf32-rounded
    fuse_rope<<<Bc * Hc * Tc, 64>>>(qs, ks, qg, kg, gate_logit, pos_offset, qcat, kt);

    // flash attention (causal), 3-stage pipelined, single barrier per tile
    cudaFuncSetAttribute(flash5, cudaFuncAttributeMaxDynamicSharedMemorySize,
                         F5_SMEM_BYTES);
    flash5<<<dim3(Tc / 128, Bc * Hc), 256, F5_SMEM_BYTES>>>(qcat, kt, vt, ao);

    // output projection (tf32 tensor cores)
    gemm_tf32<<<dim3(2048/128, MROWS/128), blk>>>(ao, Wo, out, MROWS, 2048, 2048, 0);
}

// round 7
// speedup vs baseline: 4.2580x; 1.0621x over previous
#include <cuda_runtime.h>
#include <math.h>
#include <stdint.h>

// Problem constants
#define Bc 2
#define Tc 2048
#define Dc 2048
#define Hc 16
#define MROWS (Bc*Tc)          // 4096

// ---------------- scratch (device globals; no allocation allowed) -------------
__device__ float g_qs[MROWS * 1024];
__device__ float g_ks[MROWS * 1024];
__device__ float g_qg[MROWS * 1024];
__device__ float g_kg[MROWS * 1024];
__device__ float g_vt[MROWS * 2048];           // V, tf32-rounded
__device__ float g_qcat[Bc*Hc*Tc*128];         // Q, tf32-rounded (gate+scale folded)
__device__ float g_kt  [Bc*Hc*Tc*128];         // K, tf32-rounded
__device__ float g_ao [MROWS * 2048];

// ---------------- tf32 helpers -------------------------------------------------
__device__ __forceinline__ uint32_t f2tf32(float f) {
    uint32_t u;
    asm("cvt.rna.tf32.f32 %0, %1;" : "=r"(u) : "f"(f));
    return u;
}
__device__ __forceinline__ float tf32r(float x) {
    return __uint_as_float(f2tf32(x));
}

__device__ __forceinline__ void mma_tf32(float* c,
                                         uint32_t a0, uint32_t a1, uint32_t a2, uint32_t a3,
                                         uint32_t b0, uint32_t b1) {
    asm volatile("mma.sync.aligned.m16n8k8.row.col.f32.tf32.tf32.f32 "
                 "{%0,%1,%2,%3}, {%4,%5,%6,%7}, {%8,%9}, {%0,%1,%2,%3};"
                 : "+f"(c[0]), "+f"(c[1]), "+f"(c[2]), "+f"(c[3])
                 : "r"(a0), "r"(a1), "r"(a2), "r"(a3), "r"(b0), "r"(b1));
}

__device__ __forceinline__ void cp16(void* dst, const void* src) {
    uint32_t d = (uint32_t)__cvta_generic_to_shared(dst);
    asm volatile("cp.async.cg.shared.global [%0], [%1], 16;" :: "r"(d), "l"(src));
}
__device__ __forceinline__ void cp_commit() {
    asm volatile("cp.async.commit_group;");
}
__device__ __forceinline__ void cp_wait1() {
    asm volatile("cp.async.wait_group 1;");
}
__device__ __forceinline__ void cp_wait0() {
    asm volatile("cp.async.wait_group 0;");
}

// ---------------- tf32 tensor-core GEMM: C[M,N] = A[M,K] @ B[K,N] --------------
#define TBK 16

__global__ __launch_bounds__(128, 2) void gemm_tf32(const float* __restrict__ A,
                                                    const float* __restrict__ B,
                                                    float* __restrict__ C,
                                                    int M, int N, int K, int roundC) {
    __shared__ uint32_t As[2][TBK][132];
    __shared__ uint32_t Bs[2][TBK][136];

    const int tid  = threadIdx.x;
    const int lane = tid & 31;
    const int wid  = tid >> 5;
    const int warpRow = (wid >> 1) * 64;
    const int warpCol = (wid & 1) * 64;
    const int bm = blockIdx.y * 128;
    const int bn = blockIdx.x * 128;

    const int a_r0 = tid >> 2;
    const int a_c4 = (tid & 3) * 4;
    const int b_n4 = (tid & 31) * 4;
    const int b_k0 = tid >> 5;

    float acc[4][8][4];
    #pragma unroll
    for (int i = 0; i < 4; i++)
        #pragma unroll
        for (int j = 0; j < 8; j++)
            #pragma unroll
            for (int r = 0; r < 4; r++) acc[i][j][r] = 0.f;

    float4 pa[4], pb[4];
    const int nkt = K / TBK;

    #pragma unroll
    for (int i = 0; i < 4; i++)
        pa[i] = *(const float4*)(A + (size_t)(bm + a_r0 + 32*i) * K + a_c4);
    #pragma unroll
    for (int i = 0; i < 4; i++)
        pb[i] = *(const float4*)(B + (size_t)(b_k0 + 4*i) * N + bn + b_n4);
    #pragma unroll
    for (int i = 0; i < 4; i++) {
        const int row = a_r0 + 32*i;
        As[0][a_c4+0][row] = f2tf32(pa[i].x);
        As[0][a_c4+1][row] = f2tf32(pa[i].y);
        As[0][a_c4+2][row] = f2tf32(pa[i].z);
        As[0][a_c4+3][row] = f2tf32(pa[i].w);
    }
    #pragma unroll
    for (int i = 0; i < 4; i++) {
        uint32_t* dst = &Bs[0][b_k0 + 4*i][b_n4];
        dst[0] = f2tf32(pb[i].x);
        dst[1] = f2tf32(pb[i].y);
        dst[2] = f2tf32(pb[i].z);
        dst[3] = f2tf32(pb[i].w);
    }
    __syncthreads();

    for (int kt = 0; kt < nkt; kt++) {
        const int buf = kt & 1;

        if (kt + 1 < nkt) {
            const int k0 = (kt + 1) * TBK;
            #pragma unroll
            for (int i = 0; i < 4; i++)
                pa[i] = *(const float4*)(A + (size_t)(bm + a_r0 + 32*i) * K + k0 + a_c4);
            #pragma unroll
            for (int i = 0; i < 4; i++)
                pb[i] = *(const float4*)(B + (size_t)(k0 + b_k0 + 4*i) * N + bn + b_n4);
        }

        #pragma unroll
        for (int ks = 0; ks < 2; ks++) {
            const int kb = ks * 8;
            uint32_t af[4][4], bf[8][2];
            #pragma unroll
            for (int am = 0; am < 4; am++) {
                const int r0 = warpRow + am*16 + (lane >> 2);
                af[am][0] = As[buf][kb + (lane & 3)    ][r0];
                af[am][1] = As[buf][kb + (lane & 3)    ][r0 + 8];
                af[am][2] = As[buf][kb + (lane & 3) + 4][r0];
                af[am][3] = As[buf][kb + (lane & 3) + 4][r0 + 8];
            }
            #pragma unroll
            for (int an = 0; an < 8; an++) {
                const int c0 = warpCol + an*8 + (lane >> 2);
                bf[an][0] = Bs[buf][kb + (lane & 3)    ][c0];
                bf[an][1] = Bs[buf][kb + (lane & 3) + 4][c0];
            }
            #pragma unroll
            for (int am = 0; am < 4; am++)
                #pragma unroll
                for (int an = 0; an < 8; an++)
                    mma_tf32(acc[am][an], af[am][0], af[am][1], af[am][2], af[am][3],
                             bf[an][0], bf[an][1]);
        }

        if (kt + 1 < nkt) {
            const int nb = buf ^ 1;
            #pragma unroll
            for (int i = 0; i < 4; i++) {
                const int row = a_r0 + 32*i;
                As[nb][a_c4+0][row] = f2tf32(pa[i].x);
                As[nb][a_c4+1][row] = f2tf32(pa[i].y);
                As[nb][a_c4+2][row] = f2tf32(pa[i].z);
                As[nb][a_c4+3][row] = f2tf32(pa[i].w);
            }
            #pragma unroll
            for (int i = 0; i < 4; i++) {
                uint32_t* dst = &Bs[nb][b_k0 + 4*i][b_n4];
                dst[0] = f2tf32(pb[i].x);
                dst[1] = f2tf32(pb[i].y);
                dst[2] = f2tf32(pb[i].z);
                dst[3] = f2tf32(pb[i].w);
            }
        }
        __syncthreads();
    }

    #pragma unroll
    for (int am = 0; am < 4; am++) {
        const int r0 = bm + warpRow + am*16 + (lane >> 2);
        #pragma unroll
        for (int an = 0; an < 8; an++) {
            const int c0 = bn + warpCol + an*8 + (lane & 3)*2;
            float v0 = acc[am][an][0], v1 = acc[am][an][1];
            float v2 = acc[am][an][2], v3 = acc[am][an][3];
            if (roundC) { v0 = tf32r(v0); v1 = tf32r(v1); v2 = tf32r(v2); v3 = tf32r(v3); }
            *(float2*)(C + (size_t)r0 * N + c0)       = make_float2(v0, v1);
            *(float2*)(C + (size_t)(r0 + 8) * N + c0) = make_float2(v2, v3);
        }
    }
}

// ---------------- RoPE + gate fusion: Q and K both tf32-rounded ----------------
__global__ void fuse_rope(const float* __restrict__ qs, const float* __restrict__ ks,
                          const float* __restrict__ qg, const float* __restrict__ kg,
                          const float* __restrict__ gate_logit,
                          const int* __restrict__ pos_offset,
                          float* __restrict__ qcat, float* __restrict__ kt_o) {
    const int row = blockIdx.x;              // (b*H + h)*T + t
    const int d   = threadIdx.x;             // 0..63
    const int t   = row % Tc;
    const int h   = (row / Tc) % Hc;
    const int b   = row / (Tc * Hc);

    const size_t src = ((size_t)(b * Tc + t)) * 1024 + h * 64 + d;
    const size_t dst = (size_t)row * 128;

    const float gate = 1.f / (1.f + __expf(-gate_logit[h]));
    const float scale = 0.125f;              // 1/sqrt(64)
    const float gq_sem = 2.f * gate * scale;
    const float gq_geo = (2.f - 2.f * gate) * scale;

    qcat[dst + d] = tf32r(qs[src] * gq_sem);
    kt_o[dst + d] = tf32r(ks[src]);

    if (d < 32) {
        const float inv_freq = powf(10000.f, -(float)d / 32.f);
        const float ang = ((float)t + (float)(*pos_offset)) * inv_freq;
        const float c = cosf(ang), s = sinf(ang);
        const float q1 = qg[src], q2 = qg[src + 32];
        const float k1 = kg[src], k2 = kg[src + 32];
        qcat[dst + 64 + d]      = tf32r((q1 * c - q2 * s) * gq_geo);
        qcat[dst + 64 + d + 32] = tf32r((q2 * c + q1 * s) * gq_geo);
        kt_o[dst + 64 + d]      = tf32r(k1 * c - k2 * s);
        kt_o[dst + 64 + d + 32] = tf32r(k2 * c + k1 * s);
    }
}

// ---------------- Flash attention v6 -------------------------------------------
// BM=128 (8 warps x 16 rows), BN=64. Plain tf32 QK (Q pre-rounded) + tf32 PV.
// 3-stage cp.async ring; ONE __syncthreads per tile; P in registers.
#define F6_KSTR 132
#define F6_VSTR 136
#define F6_KBUF (64*F6_KSTR)
#define F6_VBUF (64*F6_VSTR)
#define F6_STAGE (F6_KBUF + F6_VBUF)
#define F6_SMEM_FLOATS (3 * F6_STAGE)
#define F6_SMEM_BYTES  (F6_SMEM_FLOATS * 4)   // 205,824 B

__global__ __launch_bounds__(256, 1) void flash6(
    const float* __restrict__ Qc,
    const float* __restrict__ Ktg,
    const float* __restrict__ Vtg,
    float* __restrict__ Out)
{
    extern __shared__ float sm[];

    const int qb = gridDim.x - 1 - blockIdx.x;   // heavy CTAs first
    const int bh = blockIdx.y;
    const int b  = bh >> 4, h = bh & 15;
    const int tid  = threadIdx.x;
    const int lane = tid & 31;
    const int wid  = tid >> 5;
    const int g = lane >> 2;
    const int t = lane & 3;
    const int r0 = wid * 16 + g;

    const float* Qg  = Qc  + ((size_t)bh * Tc + qb * 128) * 128;
    const float* Kp  = Ktg + (size_t)bh * Tc * 128;
    const float* Vp  = Vtg + (size_t)b * Tc * 2048 + h * 128;

    // ---- stage Q through stage-0 region; convert ONCE to tf32 frags ----
    for (int i = tid; i < 4096; i += 256) {
        const int r = i >> 5, c4 = (i & 31) << 2;
        *(float4*)&sm[r * F6_KSTR + c4] = *(const float4*)(Qg + r * 128 + c4);
    }
    __syncthreads();
    uint32_t qf[16][4];
    #pragma unroll
    for (int ks = 0; ks < 16; ks++) {
        qf[ks][0] = f2tf32(sm[ r0      * F6_KSTR + ks*8 + t]);
        qf[ks][1] = f2tf32(sm[(r0 + 8) * F6_KSTR + ks*8 + t]);
        qf[ks][2] = f2tf32(sm[ r0      * F6_KSTR + ks*8 + t + 4]);
        qf[ks][3] = f2tf32(sm[(r0 + 8) * F6_KSTR + ks*8 + t + 4]);
    }
    __syncthreads();    // reads done before prefetch overwrites

    const int ntiles = 2 * qb + 2;

    // ---- prologue: prefetch tiles 0, 1 into stages 0, 1 ----
    #pragma unroll
    for (int pre = 0; pre < 2; pre++) {
        float* dK = sm + pre * F6_STAGE;
        float* dV = dK + F6_KBUF;
        #pragma unroll
        for (int j = 0; j < 8; j++) {
            const int i = tid + j * 256;
            const int r = i >> 5, c4 = (i & 31) << 2;
            const size_t krow = (size_t)(pre * 64 + r);
            cp16(&dK[r*F6_KSTR + c4], Kp + krow*128  + c4);
            cp16(&dV[r*F6_VSTR + c4], Vp + krow*2048 + c4);
        }
        cp_commit();
    }

    float oreg[16][4];
    #pragma unroll
    for (int n = 0; n < 16; n++) {
        oreg[n][0] = 0.f; oreg[n][1] = 0.f; oreg[n][2] = 0.f; oreg[n][3] = 0.f;
    }
    float M0 = -1e30f, M1 = -1e30f, L0 = 0.f, L1 = 0.f;

    const int srcA = (lane & 28) | (t >> 1);
    const int srcB = srcA + 2;
    const bool odd = (t & 1);

    int s_cur = 0, s_pre = 2;
    for (int kt = 0; kt < ntiles; kt++) {
        if (kt + 1 < ntiles) cp_wait1(); else cp_wait0();
        __syncthreads();   // kt data visible; stage s_pre free

        // ---- prefetch tile kt+2 ----
        if (kt + 2 < ntiles) {
            float* dK = sm + s_pre * F6_STAGE;
            float* dV = dK + F6_KBUF;
            #pragma unroll
            for (int j = 0; j < 8; j++) {
                const int i = tid + j * 256;
                const int r = i >> 5, c4 = (i & 31) << 2;
                const size_t krow = (size_t)((kt + 2) * 64 + r);
                cp16(&dK[r*F6_KSTR + c4], Kp + krow*128  + c4);
                cp16(&dV[r*F6_VSTR + c4], Vp + krow*2048 + c4);
            }
            cp_commit();
        }

        const uint32_t* uK = (const uint32_t*)(sm + s_cur * F6_STAGE);
        const uint32_t* uV = uK + F6_KBUF;

        // ---- S = Q K^T (plain tf32), 8 n-atoms/warp ----
        float sreg[8][4];
        #pragma unroll
        for (int n = 0; n < 8; n++) {
            sreg[n][0] = 0.f; sreg[n][1] = 0.f; sreg[n][2] = 0.f; sreg[n][3] = 0.f;
        }
        #pragma unroll
        for (int ks = 0; ks < 16; ks++) {
            const int kb = ks*8 + t;
            #pragma unroll
            for (int n = 0; n < 8; n++) {
                const int kr = n*8 + g;
                mma_tf32(sreg[n], qf[ks][0], qf[ks][1], qf[ks][2], qf[ks][3],
                         uK[kr*F6_KSTR + kb], uK[kr*F6_KSTR + kb + 4]);
            }
        }

        // ---- causal mask ----
        if (kt >= 2 * qb) {
            const int qrow0 = qb * 128 + r0;
            const int qrow1 = qrow0 + 8;
            #pragma unroll
            for (int n = 0; n < 8; n++) {
                const int c = kt * 64 + n*8 + 2*t;
                if (c     > qrow0) sreg[n][0] = -1e30f;
                if (c + 1 > qrow0) sreg[n][1] = -1e30f;
                if (c     > qrow1) sreg[n][2] = -1e30f;
                if (c + 1 > qrow1) sreg[n][3] = -1e30f;
            }
        }

        // ---- online softmax (rows r0, r0+8; quad reduction) ----
        float mx0 = -1e30f, mx1 = -1e30f;
        #pragma unroll
        for (int n = 0; n < 8; n++) {
            mx0 = fmaxf(mx0, fmaxf(sreg[n][0], sreg[n][1]));
            mx1 = fmaxf(mx1, fmaxf(sreg[n][2], sreg[n][3]));
        }
        mx0 = fmaxf(mx0, __shfl_xor_sync(0xffffffffu, mx0, 1));
        mx0 = fmaxf(mx0, __shfl_xor_sync(0xffffffffu, mx0, 2));
        mx1 = fmaxf(mx1, __shfl_xor_sync(0xffffffffu, mx1, 1));
        mx1 = fmaxf(mx1, __shfl_xor_sync(0xffffffffu, mx1, 2));
        const float mn0 = fmaxf(M0, mx0), mn1 = fmaxf(M1, mx1);
        const float sc0 = __expf(M0 - mn0), sc1 = __expf(M1 - mn1);
        float sum0 = 0.f, sum1 = 0.f;
        #pragma unroll
        for (int n = 0; n < 8; n++) {
            sreg[n][0] = __expf(sreg[n][0] - mn0); sum0 += sreg[n][0];
            sreg[n][1] = __expf(sreg[n][1] - mn0); sum0 += sreg[n][1];
            sreg[n][2] = __expf(sreg[n][2] - mn1); sum1 += sreg[n][2];
            sreg[n][3] = __expf(sreg[n][3] - mn1); sum1 += sreg[n][3];
        }
        sum0 += __shfl_xor_sync(0xffffffffu, sum0, 1);
        sum0 += __shfl_xor_sync(0xffffffffu, sum0, 2);
        sum1 += __shfl_xor_sync(0xffffffffu, sum1, 1);
        sum1 += __shfl_xor_sync(0xffffffffu, sum1, 2);
        M0 = mn0; M1 = mn1;
        L0 = L0 * sc0 + sum0;
        L1 = L1 * sc1 + sum1;
        #pragma unroll
        for (int n = 0; n < 16; n++) {
            oreg[n][0] *= sc0; oreg[n][1] *= sc0;
            oreg[n][2] *= sc1; oreg[n][3] *= sc1;
        }

        // ---- O += P V (tf32); P C-frag -> A-frag via shuffles ----
        #pragma unroll
        for (int ka = 0; ka < 8; ka++) {
            const float v00 = sreg[ka][0], v01 = sreg[ka][1];
            const float v10 = sreg[ka][2], v11 = sreg[ka][3];
            float w0 = __shfl_sync(0xffffffffu, v00, srcA);
            float w1 = __shfl_sync(0xffffffffu, v01, srcA);
            float w2 = __shfl_sync(0xffffffffu, v10, srcA);
            float w3 = __shfl_sync(0xffffffffu, v11, srcA);
            float w4 = __shfl_sync(0xffffffffu, v00, srcB);
            float w5 = __shfl_sync(0xffffffffu, v01, srcB);
            float w6 = __shfl_sync(0xffffffffu, v10, srcB);
            float w7 = __shfl_sync(0xffffffffu, v11, srcB);
            const uint32_t a0 = f2tf32(odd ? w1 : w0);
            const uint32_t a1 = f2tf32(odd ? w3 : w2);
            const uint32_t a2 = f2tf32(odd ? w5 : w4);
            const uint32_t a3 = f2tf32(odd ? w7 : w6);
            const int kr0 = (ka*8 + t) * F6_VSTR;
            const int kr1 = (ka*8 + t + 4) * F6_VSTR;
            #pragma unroll
            for (int n = 0; n < 16; n++) {
                const int vc = n*8 + g;
                mma_tf32(oreg[n], a0, a1, a2, a3, uV[kr0 + vc], uV[kr1 + vc]);
            }
        }

        // rotate stages
        s_cur = (s_cur == 2) ? 0 : s_cur + 1;
        s_pre = (s_pre == 2) ? 0 : s_pre + 1;
    }

    // ---- epilogue ----
    const float inv0 = 1.f / L0, inv1 = 1.f / L1;
    const size_t row0 = (size_t)b * Tc + qb * 128 + r0;
    #pragma unroll
    for (int n = 0; n < 16; n++) {
        const int col = h * 128 + n*8 + 2*t;
        *(float2*)(Out +  row0      * 2048 + col) = make_float2(oreg[n][0]*inv0, oreg[n][1]*inv0);
        *(float2*)(Out + (row0 + 8) * 2048 + col) = make_float2(oreg[n][2]*inv1, oreg[n][3]*inv1);
    }
}

// ---------------- host launch --------------------------------------------------
extern "C" void kernel_launch(void* const* d_in, const int* in_sizes, int n_in,
                              void* d_out, int out_size) {
    const float* x          = (const float*)d_in[0];
    const float* Wq_sem     = (const float*)d_in[1];
    const float* Wk_sem     = (const float*)d_in[2];
    const float* Wq_geo     = (const float*)d_in[3];
    const float* Wk_geo     = (const float*)d_in[4];
    const float* Wv         = (const float*)d_in[5];
    const float* Wo         = (const float*)d_in[6];
    const float* gate_logit = (const float*)d_in[7];
    const int*   pos_offset = (const int*)d_in[8];
    float* out = (float*)d_out;

    float *qs, *ks, *qg, *kg, *vt, *qcat, *kt, *ao;
    cudaGetSymbolAddress((void**)&qs,   g_qs);
    cudaGetSymbolAddress((void**)&ks,   g_ks);
    cudaGetSymbolAddress((void**)&qg,   g_qg);
    cudaGetSymbolAddress((void**)&kg,   g_kg);
    cudaGetSymbolAddress((void**)&vt,   g_vt);
    cudaGetSymbolAddress((void**)&qcat, g_qcat);
    cudaGetSymbolAddress((void**)&kt,   g_kt);
    cudaGetSymbolAddress((void**)&ao,   g_ao);

    const dim3 blk(128);

    // projections (tf32 tensor cores); V rounded to tf32 in epilogue
    gemm_tf32<<<dim3(1024/128, MROWS/128), blk>>>(x, Wq_sem, qs, MROWS, 1024, 2048, 0);
    gemm_tf32<<<dim3(1024/128, MROWS/128), blk>>>(x, Wk_sem, ks, MROWS, 1024, 2048, 0);
    gemm_tf32<<<dim3(1024/128, MROWS/128), blk>>>(x, Wq_geo, qg, MROWS, 1024, 2048, 0);
    gemm_tf32<<<dim3(1024/128, MROWS/128), blk>>>(x, Wk_geo, kg, MROWS, 1024, 2048, 0);
    gemm_tf32<<<dim3(2048/128, MROWS/128), blk>>>(x, Wv,     vt, MROWS, 2048, 2048, 1);

    // RoPE + gate + scale fusion; Q and K emitted tf32-rounded
    fuse_rope<<<Bc * Hc * Tc, 64>>>(qs, ks, qg, kg, gate_logit, pos_offset, qcat, kt);

    // flash attention (causal), plain tf32 QK + PV, 3-stage pipeline
    cudaFuncSetAttribute(flash6, cudaFuncAttributeMaxDynamicSharedMemorySize,
                         F6_SMEM_BYTES);
    flash6<<<dim3(Tc / 128, Bc * Hc), 256, F6_SMEM_BYTES>>>(qcat, kt, vt, ao);

    // output projection (tf32 tensor cores)
    gemm_tf32<<<dim3(2048/128, MROWS/128), blk>>>(ao, Wo, out, MROWS, 2048, 2048, 0);
}